// round 1
// baseline (speedup 1.0000x reference)
#include <cuda_runtime.h>
#include <math.h>

// Problem dims
#define BT_ROWS 8192   // B*T
#define DIM     1024
#define NH      16
#define HDIM    64
#define TCTX    2048
#define NB      4
#define D3      3072
#define D4      4096

// ---------------- scratch (device globals; no allocation allowed) ----------
__device__ float g_xn  [BT_ROWS * DIM];   // LN1 output
__device__ float g_wqkv[DIM * D3];        // repacked [D, 3D] qkv weights
__device__ float g_qkv [BT_ROWS * D3];    // q|k|v per row
__device__ float g_attn[BT_ROWS * DIM];   // attention output (concat heads)
__device__ float g_x1  [BT_ROWS * DIM];   // x after attn residual
__device__ float g_xn2 [BT_ROWS * DIM];   // LN2 output
__device__ float g_h   [BT_ROWS * D4];    // MLP hidden

// ---------------- LayerNorm: one block per row, 256 threads, float4 --------
__global__ void __launch_bounds__(256) ln_kernel(const float* __restrict__ x,
                                                 const float* __restrict__ w,
                                                 const float* __restrict__ b,
                                                 float* __restrict__ out) {
    int row = blockIdx.x;
    int tid = threadIdx.x;
    const float4* xr = reinterpret_cast<const float4*>(x + (size_t)row * DIM);
    float4 v = xr[tid];
    float s  = v.x + v.y + v.z + v.w;
    float ss = v.x * v.x + v.y * v.y + v.z * v.z + v.w * v.w;
#pragma unroll
    for (int off = 16; off > 0; off >>= 1) {
        s  += __shfl_xor_sync(0xffffffffu, s,  off);
        ss += __shfl_xor_sync(0xffffffffu, ss, off);
    }
    __shared__ float sm[8], sm2[8];
    __shared__ float mu_sh, rstd_sh;
    int wid = tid >> 5, lane = tid & 31;
    if (lane == 0) { sm[wid] = s; sm2[wid] = ss; }
    __syncthreads();
    if (tid == 0) {
        float ts = 0.f, tss = 0.f;
#pragma unroll
        for (int i = 0; i < 8; i++) { ts += sm[i]; tss += sm2[i]; }
        float mu  = ts * (1.0f / DIM);
        float var = tss * (1.0f / DIM) - mu * mu;
        mu_sh   = mu;
        rstd_sh = rsqrtf(var + 1e-5f);
    }
    __syncthreads();
    float mu = mu_sh, rstd = rstd_sh;
    float4 wv = reinterpret_cast<const float4*>(w)[tid];
    float4 bv = reinterpret_cast<const float4*>(b)[tid];
    float4 o;
    o.x = (v.x - mu) * rstd * wv.x + bv.x;
    o.y = (v.y - mu) * rstd * wv.y + bv.y;
    o.z = (v.z - mu) * rstd * wv.z + bv.z;
    o.w = (v.w - mu) * rstd * wv.w + bv.w;
    reinterpret_cast<float4*>(out + (size_t)row * DIM)[tid] = o;
}

// ---------------- repack wq/wk/wv [H,D,HD] -> Wcat [D, 3D] -----------------
// Wcat[d, m*D + h*HD + e] = w_m[h, d, e]
__global__ void __launch_bounds__(256) repack_kernel(const float* __restrict__ wq,
                                                     const float* __restrict__ wk,
                                                     const float* __restrict__ wv,
                                                     float* __restrict__ out) {
    int i = blockIdx.x * 256 + threadIdx.x;       // 0 .. 3*2^20-1
    int e = i & 63;
    int d = (i >> 6) & 1023;
    int h = (i >> 16) & 15;
    int m = i >> 20;
    const float* src = (m == 0) ? wq : (m == 1) ? wk : wv;
    out[(size_t)d * D3 + m * DIM + h * HDIM + e] = src[((size_t)h * DIM + d) * HDIM + e];
}

// ---------------- SGEMM: C[M,N] = A[M,K] @ B[K,N] (+bias)(+res)(relu) ------
// 128x128x8 tile, 256 threads, 8x8 per thread
__global__ void __launch_bounds__(256) sgemm_kernel(
    const float* __restrict__ A, const float* __restrict__ B, float* __restrict__ C,
    const float* __restrict__ bias, const float* __restrict__ res, int relu,
    int M, int N, int K) {
    __shared__ float As[8][128];
    __shared__ float Bs[8][128];
    int tid = threadIdx.x;
    int bm = blockIdx.y * 128, bn = blockIdx.x * 128;
    int rb = (tid >> 4) * 8;         // row base within tile
    int cb = (tid & 15) * 8;         // col base within tile
    int a_row = tid >> 1, a_k = (tid & 1) * 4;
    int b_k = tid >> 5, b_n = (tid & 31) * 4;
    const float* Ap = A + (size_t)(bm + a_row) * K + a_k;
    const float* Bp = B + (size_t)b_k * N + bn + b_n;
    float acc[8][8] = {};
    for (int kt = 0; kt < K; kt += 8) {
        float4 av = *reinterpret_cast<const float4*>(Ap + kt);
        float4 bv = *reinterpret_cast<const float4*>(Bp + (size_t)kt * N);
        As[a_k + 0][a_row] = av.x;
        As[a_k + 1][a_row] = av.y;
        As[a_k + 2][a_row] = av.z;
        As[a_k + 3][a_row] = av.w;
        *reinterpret_cast<float4*>(&Bs[b_k][b_n]) = bv;
        __syncthreads();
#pragma unroll
        for (int k = 0; k < 8; k++) {
            float ar[8], br[8];
            *reinterpret_cast<float4*>(ar)     = *reinterpret_cast<const float4*>(&As[k][rb]);
            *reinterpret_cast<float4*>(ar + 4) = *reinterpret_cast<const float4*>(&As[k][rb + 4]);
            *reinterpret_cast<float4*>(br)     = *reinterpret_cast<const float4*>(&Bs[k][cb]);
            *reinterpret_cast<float4*>(br + 4) = *reinterpret_cast<const float4*>(&Bs[k][cb + 4]);
#pragma unroll
            for (int i = 0; i < 8; i++)
#pragma unroll
                for (int j = 0; j < 8; j++)
                    acc[i][j] += ar[i] * br[j];
        }
        __syncthreads();
    }
#pragma unroll
    for (int i = 0; i < 8; i++) {
        int m = bm + rb + i;
#pragma unroll
        for (int j = 0; j < 8; j++) {
            int n = bn + cb + j;
            float v = acc[i][j];
            if (bias) v += bias[n];
            if (res)  v += res[(size_t)m * N + n];
            if (relu) v = fmaxf(v, 0.f);
            C[(size_t)m * N + n] = v;
        }
    }
}

// ---------------- Flash attention (fp32, causal) ---------------------------
// grid: (T/64, B*H); block: 256 threads. BQ=64, BKV=32, HD=64.
__global__ void __launch_bounds__(256) attn_kernel(const float* __restrict__ qkv,
                                                   float* __restrict__ attn_out) {
    __shared__ float Qs[64][65];
    __shared__ float Ks[32][65];
    __shared__ float Vs[32][65];
    __shared__ float Ps[64][33];
    __shared__ float m_s[64], l_s[64], alpha_s[64];

    int tid = threadIdx.x;
    int bh = blockIdx.y;
    int b = bh >> 4, h = bh & 15;
    int qt = blockIdx.x;
    int t0 = qt * 64;
    const float* base = qkv + (size_t)b * TCTX * D3 + h * HDIM;

    // load Q tile [64 x 64]
    for (int i = tid; i < 64 * 64; i += 256) {
        int r = i >> 6, e = i & 63;
        Qs[r][e] = base[(size_t)(t0 + r) * D3 + e];
    }
    if (tid < 64) { m_s[tid] = -1e30f; l_s[tid] = 0.f; }

    // S mapping: 8x32 thread grid, each thread 2 rows x 4 cols
    int sx = tid & 7, sy = tid >> 3;
    int r0 = sy * 2, c0 = sx * 4;
    // O mapping: 16x16 thread grid, each thread 4 rows x 4 cols
    int ox = tid & 15, oy = tid >> 4;
    float o[4][4] = {};
    __syncthreads();

    int ntiles = (t0 + 64) / 32;
    for (int kt = 0; kt < ntiles; kt++) {
        int kv0 = kt * 32;
        float oldm[2], oldl[2];
        oldm[0] = m_s[r0];     oldm[1] = m_s[r0 + 1];
        oldl[0] = l_s[r0];     oldl[1] = l_s[r0 + 1];

        // load K,V tiles [32 x 64]
        for (int i = tid; i < 32 * 64; i += 256) {
            int s = i >> 6, e = i & 63;
            Ks[s][e] = base[(size_t)(kv0 + s) * D3 + DIM + e];
            Vs[s][e] = base[(size_t)(kv0 + s) * D3 + 2 * DIM + e];
        }
        __syncthreads();

        // S = Q K^T
        float acc[2][4] = {};
#pragma unroll 8
        for (int k = 0; k < 64; k++) {
            float q0 = Qs[r0][k], q1 = Qs[r0 + 1][k];
#pragma unroll
            for (int j = 0; j < 4; j++) {
                float kv = Ks[c0 + j][k];
                acc[0][j] += q0 * kv;
                acc[1][j] += q1 * kv;
            }
        }
        // scale + causal mask
#pragma unroll
        for (int i2 = 0; i2 < 2; i2++) {
            int qg = t0 + r0 + i2;
#pragma unroll
            for (int j = 0; j < 4; j++) {
                int sg = kv0 + c0 + j;
                acc[i2][j] = (sg <= qg) ? acc[i2][j] * 0.125f : -1e30f;
            }
        }
        // online softmax per row (2 rows per thread)
#pragma unroll
        for (int i2 = 0; i2 < 2; i2++) {
            int r = r0 + i2;
            float mx = fmaxf(fmaxf(acc[i2][0], acc[i2][1]), fmaxf(acc[i2][2], acc[i2][3]));
#pragma unroll
            for (int off = 4; off > 0; off >>= 1)
                mx = fmaxf(mx, __shfl_xor_sync(0xffffffffu, mx, off));
            float newm = fmaxf(oldm[i2], mx);
            float p[4], rsum = 0.f;
#pragma unroll
            for (int j = 0; j < 4; j++) {
                p[j] = __expf(acc[i2][j] - newm);
                rsum += p[j];
            }
#pragma unroll
            for (int off = 4; off > 0; off >>= 1)
                rsum += __shfl_xor_sync(0xffffffffu, rsum, off);
            float alpha = __expf(oldm[i2] - newm);
#pragma unroll
            for (int j = 0; j < 4; j++) Ps[r][c0 + j] = p[j];
            if (sx == 0) {
                m_s[r] = newm;
                l_s[r] = alpha * oldl[i2] + rsum;
                alpha_s[r] = alpha;
            }
        }
        __syncthreads();

        // O = O*alpha + P @ V
        float al[4];
#pragma unroll
        for (int i = 0; i < 4; i++) {
            al[i] = alpha_s[oy * 4 + i];
#pragma unroll
            for (int j = 0; j < 4; j++) o[i][j] *= al[i];
        }
#pragma unroll 4
        for (int s = 0; s < 32; s++) {
            float pv[4], vv[4];
#pragma unroll
            for (int i = 0; i < 4; i++) pv[i] = Ps[oy * 4 + i][s];
#pragma unroll
            for (int j = 0; j < 4; j++) vv[j] = Vs[s][ox * 4 + j];
#pragma unroll
            for (int i = 0; i < 4; i++)
#pragma unroll
                for (int j = 0; j < 4; j++)
                    o[i][j] += pv[i] * vv[j];
        }
        __syncthreads();
    }

    // normalize and write: attn_out[b, t, h*HD + e]
#pragma unroll
    for (int i = 0; i < 4; i++) {
        int r = oy * 4 + i;
        float inv = 1.0f / l_s[r];
        size_t rowoff = (size_t)(b * TCTX + t0 + r) * DIM + h * HDIM + ox * 4;
#pragma unroll
        for (int j = 0; j < 4; j++)
            attn_out[rowoff + j] = o[i][j] * inv;
    }
}

// ---------------- launch ----------------------------------------------------
extern "C" void kernel_launch(void* const* d_in, const int* in_sizes, int n_in,
                              void* d_out, int out_size) {
    const float* x      = (const float*)d_in[0];
    const float* ln1_w  = (const float*)d_in[1];
    const float* ln1_b  = (const float*)d_in[2];
    const float* wq     = (const float*)d_in[3];
    const float* wk     = (const float*)d_in[4];
    const float* wv     = (const float*)d_in[5];
    const float* w_proj = (const float*)d_in[6];
    const float* b_proj = (const float*)d_in[7];
    const float* ln2_w  = (const float*)d_in[8];
    const float* ln2_b  = (const float*)d_in[9];
    const float* w1     = (const float*)d_in[10];
    const float* b1     = (const float*)d_in[11];
    const float* w2     = (const float*)d_in[12];
    const float* b2     = (const float*)d_in[13];
    float* out = (float*)d_out;

    float *xn, *wqkv, *qkv, *attn, *x1, *xn2, *hbuf;
    cudaGetSymbolAddress((void**)&xn,   g_xn);
    cudaGetSymbolAddress((void**)&wqkv, g_wqkv);
    cudaGetSymbolAddress((void**)&qkv,  g_qkv);
    cudaGetSymbolAddress((void**)&attn, g_attn);
    cudaGetSymbolAddress((void**)&x1,   g_x1);
    cudaGetSymbolAddress((void**)&xn2,  g_xn2);
    cudaGetSymbolAddress((void**)&hbuf, g_h);

    // 1. LN1
    ln_kernel<<<BT_ROWS, 256>>>(x, ln1_w, ln1_b, xn);
    // 2. repack qkv weights -> [D, 3D]
    repack_kernel<<<(3 * DIM * DIM) / 256, 256>>>(wq, wk, wv, wqkv);
    // 3. fused QKV gemm: [8192,1024] @ [1024,3072]
    sgemm_kernel<<<dim3(D3 / 128, BT_ROWS / 128), 256>>>(
        xn, wqkv, qkv, nullptr, nullptr, 0, BT_ROWS, D3, DIM);
    // 4. causal flash attention
    attn_kernel<<<dim3(TCTX / 64, NB * NH), 256>>>(qkv, attn);
    // 5. out proj + bias + residual(x)
    sgemm_kernel<<<dim3(DIM / 128, BT_ROWS / 128), 256>>>(
        attn, w_proj, x1, b_proj, x, 0, BT_ROWS, DIM, DIM);
    // 6. LN2
    ln_kernel<<<BT_ROWS, 256>>>(x1, ln2_w, ln2_b, xn2);
    // 7. MLP up + bias + relu
    sgemm_kernel<<<dim3(D4 / 128, BT_ROWS / 128), 256>>>(
        xn2, w1, hbuf, b1, nullptr, 1, BT_ROWS, D4, DIM);
    // 8. MLP down + bias + residual(x1) -> out
    sgemm_kernel<<<dim3(DIM / 128, BT_ROWS / 128), 256>>>(
        hbuf, w2, out, b2, x1, 0, BT_ROWS, DIM, D4);
}

// round 3
// speedup vs baseline: 2.0436x; 2.0436x over previous
#include <cuda_runtime.h>
#include <cuda_bf16.h>
#include <cstdint>
#include <math.h>

#define BT_ROWS 8192   // B*T
#define DIM     1024
#define NH      16
#define HDIM    64
#define TCTX    2048
#define NB      4
#define D3      3072
#define D4      4096

// ---------------- scratch (device globals) ---------------------------------
__device__ float g_qkv[BT_ROWS * D3];     // fp32 qkv for attention
__device__ float g_x1 [BT_ROWS * DIM];    // x after attn residual (fp32)
__device__ __nv_bfloat16 g_xn_hi [BT_ROWS * DIM], g_xn_lo [BT_ROWS * DIM];
__device__ __nv_bfloat16 g_at_hi [BT_ROWS * DIM], g_at_lo [BT_ROWS * DIM];
__device__ __nv_bfloat16 g_xn2_hi[BT_ROWS * DIM], g_xn2_lo[BT_ROWS * DIM];
__device__ __nv_bfloat16 g_h_hi  [(size_t)BT_ROWS * D4], g_h_lo[(size_t)BT_ROWS * D4];
__device__ __nv_bfloat16 g_wqkv_hi[D3 * DIM], g_wqkv_lo[D3 * DIM];   // [N=3072, K=1024]
__device__ __nv_bfloat16 g_wp_hi [DIM * DIM], g_wp_lo [DIM * DIM];   // [N=1024, K=1024]
__device__ __nv_bfloat16 g_w1_hi [D4 * DIM],  g_w1_lo [D4 * DIM];    // [N=4096, K=1024]
__device__ __nv_bfloat16 g_w2_hi [DIM * D4],  g_w2_lo [DIM * D4];    // [N=1024, K=4096]

// ---------------- PTX helpers (sm_80-era ISA only; no tcgen05) -------------
__device__ __forceinline__ uint32_t smem_u32(const void* p) {
    return (uint32_t)__cvta_generic_to_shared(p);
}
__device__ __forceinline__ void ldgsts16(uint32_t s, const void* g) {
    asm volatile("cp.async.cg.shared.global [%0], [%1], 16;" :: "r"(s), "l"(g));
}
__device__ __forceinline__ void cp_commit() {
    asm volatile("cp.async.commit_group;" ::: "memory");
}
__device__ __forceinline__ void cp_wait1() {
    asm volatile("cp.async.wait_group 1;" ::: "memory");
}
__device__ __forceinline__ void ldm_x4(uint32_t* r, uint32_t addr) {
    asm volatile("ldmatrix.sync.aligned.m8n8.x4.shared.b16 {%0,%1,%2,%3}, [%4];"
                 : "=r"(r[0]), "=r"(r[1]), "=r"(r[2]), "=r"(r[3]) : "r"(addr));
}
__device__ __forceinline__ void ldm_x2(uint32_t* r, uint32_t addr) {
    asm volatile("ldmatrix.sync.aligned.m8n8.x2.shared.b16 {%0,%1}, [%2];"
                 : "=r"(r[0]), "=r"(r[1]) : "r"(addr));
}
__device__ __forceinline__ void mma16816(float* d, const uint32_t* a, const uint32_t* b) {
    asm volatile("mma.sync.aligned.m16n8k16.row.col.f32.bf16.bf16.f32 "
                 "{%0,%1,%2,%3}, {%4,%5,%6,%7}, {%8,%9}, {%0,%1,%2,%3};"
                 : "+f"(d[0]), "+f"(d[1]), "+f"(d[2]), "+f"(d[3])
                 : "r"(a[0]), "r"(a[1]), "r"(a[2]), "r"(a[3]), "r"(b[0]), "r"(b[1]));
}

// ---------------- LayerNorm -> bf16 hi/lo split ----------------------------
__global__ void __launch_bounds__(256) ln_kernel(const float* __restrict__ x,
                                                 const float* __restrict__ w,
                                                 const float* __restrict__ b,
                                                 __nv_bfloat16* __restrict__ ohi,
                                                 __nv_bfloat16* __restrict__ olo) {
    int row = blockIdx.x;
    int tid = threadIdx.x;
    const float4* xr = reinterpret_cast<const float4*>(x + (size_t)row * DIM);
    float4 v = xr[tid];
    float s  = v.x + v.y + v.z + v.w;
    float ss = v.x * v.x + v.y * v.y + v.z * v.z + v.w * v.w;
#pragma unroll
    for (int off = 16; off > 0; off >>= 1) {
        s  += __shfl_xor_sync(0xffffffffu, s,  off);
        ss += __shfl_xor_sync(0xffffffffu, ss, off);
    }
    __shared__ float sm[8], sm2[8];
    __shared__ float mu_sh, rstd_sh;
    int wid = tid >> 5, lane = tid & 31;
    if (lane == 0) { sm[wid] = s; sm2[wid] = ss; }
    __syncthreads();
    if (tid == 0) {
        float ts = 0.f, tss = 0.f;
#pragma unroll
        for (int i = 0; i < 8; i++) { ts += sm[i]; tss += sm2[i]; }
        float mu  = ts * (1.0f / DIM);
        float var = tss * (1.0f / DIM) - mu * mu;
        mu_sh   = mu;
        rstd_sh = rsqrtf(var + 1e-5f);
    }
    __syncthreads();
    float mu = mu_sh, rstd = rstd_sh;
    float4 wv = reinterpret_cast<const float4*>(w)[tid];
    float4 bv = reinterpret_cast<const float4*>(b)[tid];
    float o[4];
    o[0] = (v.x - mu) * rstd * wv.x + bv.x;
    o[1] = (v.y - mu) * rstd * wv.y + bv.y;
    o[2] = (v.z - mu) * rstd * wv.z + bv.z;
    o[3] = (v.w - mu) * rstd * wv.w + bv.w;
    __nv_bfloat16 hh[4], ll[4];
#pragma unroll
    for (int j = 0; j < 4; j++) {
        hh[j] = __float2bfloat16(o[j]);
        ll[j] = __float2bfloat16(o[j] - __bfloat162float(hh[j]));
    }
    size_t base = (size_t)row * DIM + tid * 4;
    *reinterpret_cast<uint2*>(ohi + base) = *reinterpret_cast<uint2*>(hh);
    *reinterpret_cast<uint2*>(olo + base) = *reinterpret_cast<uint2*>(ll);
}

// ---------------- weight transpose + split: [R,C] fp32 -> [C,R] bf16 hi/lo --
__global__ void __launch_bounds__(256) tsplit_kernel(const float* __restrict__ src,
                                                     __nv_bfloat16* __restrict__ dhi,
                                                     __nv_bfloat16* __restrict__ dlo,
                                                     int R, int C) {
    __shared__ float t[32][33];
    int c0 = blockIdx.x * 32, r0 = blockIdx.y * 32;
    int x = threadIdx.x & 31, y = threadIdx.x >> 5;
#pragma unroll
    for (int i = 0; i < 32; i += 8)
        t[y + i][x] = src[(size_t)(r0 + y + i) * C + c0 + x];
    __syncthreads();
#pragma unroll
    for (int i = 0; i < 32; i += 8) {
        float v = t[x][y + i];
        size_t o = (size_t)(c0 + y + i) * R + r0 + x;
        __nv_bfloat16 hh = __float2bfloat16(v);
        dhi[o] = hh;
        dlo[o] = __float2bfloat16(v - __bfloat162float(hh));
    }
}

// ---------------- qkv weights [H,D,HD]x3 -> [3072, 1024] bf16 hi/lo --------
__global__ void __launch_bounds__(256) qkv_tsplit_kernel(const float* __restrict__ wq,
                                                         const float* __restrict__ wk,
                                                         const float* __restrict__ wv,
                                                         __nv_bfloat16* __restrict__ dhi,
                                                         __nv_bfloat16* __restrict__ dlo) {
    __shared__ float t[32][33];
    int k0 = blockIdx.x * 32;
    int n0 = blockIdx.y * 32;
    int m = n0 >> 10, h = (n0 >> 6) & 15, e0 = n0 & 63;
    const float* src = (m == 0) ? wq : (m == 1) ? wk : wv;
    int x = threadIdx.x & 31, y = threadIdx.x >> 5;
#pragma unroll
    for (int j = 0; j < 32; j += 8)
        t[y + j][x] = src[((size_t)h * DIM + k0 + y + j) * HDIM + e0 + x];
    __syncthreads();
#pragma unroll
    for (int i = 0; i < 32; i += 8) {
        float v = t[x][y + i];           // src[h][k0+x][e0+y+i]
        size_t o = (size_t)(n0 + y + i) * DIM + k0 + x;
        __nv_bfloat16 hh = __float2bfloat16(v);
        dhi[o] = hh;
        dlo[o] = __float2bfloat16(v - __bfloat162float(hh));
    }
}

// ---------------- MMA GEMM: C[M,N] = A[M,K] @ B[N,K]^T ---------------------
// bf16x3 split (AhiBhi + AloBhi + AhiBlo), fp32 accum via mma.m16n8k16.
// 128x128x32 CTA tile, 8 warps (2x4), warp tile 64x32, 3-stage cp.async.
#define PADB    80      // padded row stride in bytes (32 bf16 + 8 pad)
#define TILE_B  (128 * PADB)            // 10240 B per tile
#define STAGE_B (4 * TILE_B)            // Ahi|Alo|Bhi|Blo = 40960 B
#define NSTAGE  3
#define GSMEM   (NSTAGE * STAGE_B)      // 122880 B

__device__ __forceinline__ void stage_load(uint32_t sbase,
                                           const __nv_bfloat16* __restrict__ Ahi,
                                           const __nv_bfloat16* __restrict__ Alo,
                                           const __nv_bfloat16* __restrict__ Bhi,
                                           const __nv_bfloat16* __restrict__ Blo,
                                           int bm, int bn, int k0, int K, int tid) {
#pragma unroll
    for (int p = 0; p < 2; p++) {
        int idx = tid + (p << 8);
        int row = idx >> 2;
        int c16 = idx & 3;
        uint32_t soff = (uint32_t)row * PADB + (c16 << 4);
        size_t ga = (size_t)(bm + row) * K + k0 + (c16 << 3);
        size_t gb = (size_t)(bn + row) * K + k0 + (c16 << 3);
        ldgsts16(sbase + soff,              Ahi + ga);
        ldgsts16(sbase + TILE_B + soff,     Alo + ga);
        ldgsts16(sbase + 2 * TILE_B + soff, Bhi + gb);
        ldgsts16(sbase + 3 * TILE_B + soff, Blo + gb);
    }
}

__global__ void __launch_bounds__(256, 1) gemm_mma(
    const __nv_bfloat16* __restrict__ Ahi, const __nv_bfloat16* __restrict__ Alo,
    const __nv_bfloat16* __restrict__ Bhi, const __nv_bfloat16* __restrict__ Blo,
    float* __restrict__ C, __nv_bfloat16* __restrict__ Chi, __nv_bfloat16* __restrict__ Clo,
    const float* __restrict__ bias, const float* __restrict__ res, int relu,
    int M, int N, int K) {
    extern __shared__ char dsm[];
    int tid  = threadIdx.x;
    int wid  = tid >> 5;
    int lane = tid & 31;
    int bm = blockIdx.y * 128, bn = blockIdx.x * 128;
    int wm = (wid >> 2) * 64;      // warp row offset in tile
    int wn = (wid & 3) * 32;       // warp col offset in tile

    uint32_t sb = smem_u32(dsm);
    const int KT = K >> 5;         // k-tiles of 32

    float acc[4][4][4] = {};       // [mi][ni][reg]

    // prologue: stages 0..NSTAGE-2
#pragma unroll
    for (int s = 0; s < NSTAGE - 1; s++) {
        stage_load(sb + s * STAGE_B, Ahi, Alo, Bhi, Blo, bm, bn, s << 5, K, tid);
        cp_commit();
    }
    cp_wait1();
    __syncthreads();

    // ldmatrix per-lane address components
    int arow = lane & 15;
    int acolb = (lane >> 4) << 4;              // (lane/16)*8 elems * 2B
    int brow = lane & 7;
    int bcolb = ((lane >> 3) & 1) << 4;

    for (int kt = 0; kt < KT; kt++) {
        uint32_t st = sb + (uint32_t)(kt % NSTAGE) * STAGE_B;
#pragma unroll
        for (int ks = 0; ks < 2; ks++) {
            int kb = ks << 5;                  // 16 elems = 32 bytes
            uint32_t ahi[4][4], alo[4][4], bhi[4][2], blo[4][2];
#pragma unroll
            for (int mi = 0; mi < 4; mi++) {
                uint32_t ra = st + (uint32_t)(wm + mi * 16 + arow) * PADB + kb + acolb;
                ldm_x4(ahi[mi], ra);
                ldm_x4(alo[mi], ra + TILE_B);
            }
#pragma unroll
            for (int ni = 0; ni < 4; ni++) {
                uint32_t rb = st + 2 * TILE_B + (uint32_t)(wn + ni * 8 + brow) * PADB + kb + bcolb;
                ldm_x2(bhi[ni], rb);
                ldm_x2(blo[ni], rb + TILE_B);
            }
#pragma unroll
            for (int mi = 0; mi < 4; mi++)
#pragma unroll
                for (int ni = 0; ni < 4; ni++) {
                    mma16816(acc[mi][ni], ahi[mi], bhi[ni]);
                    mma16816(acc[mi][ni], alo[mi], bhi[ni]);
                    mma16816(acc[mi][ni], ahi[mi], blo[ni]);
                }
        }
        // issue next stage (slot was consumed at iteration kt-1; all warps
        // passed the trailing __syncthreads since then)
        int ktn = kt + NSTAGE - 1;
        if (ktn < KT)
            stage_load(sb + (uint32_t)(ktn % NSTAGE) * STAGE_B,
                       Ahi, Alo, Bhi, Blo, bm, bn, ktn << 5, K, tid);
        cp_commit();   // empty group in tail keeps wait semantics uniform
        cp_wait1();
        __syncthreads();
    }

    // epilogue
    int gr = lane >> 2;
    int gc = (lane & 3) << 1;
#pragma unroll
    for (int mi = 0; mi < 4; mi++) {
#pragma unroll
        for (int rr = 0; rr < 2; rr++) {
            int m = bm + wm + mi * 16 + rr * 8 + gr;
            size_t crow = (size_t)m * N;
#pragma unroll
            for (int ni = 0; ni < 4; ni++) {
                int n = bn + wn + ni * 8 + gc;
                float v0 = acc[mi][ni][rr * 2 + 0];
                float v1 = acc[mi][ni][rr * 2 + 1];
                if (bias) {
                    float2 bv = *reinterpret_cast<const float2*>(bias + n);
                    v0 += bv.x; v1 += bv.y;
                }
                if (res) {
                    float2 rv = *reinterpret_cast<const float2*>(res + crow + n);
                    v0 += rv.x; v1 += rv.y;
                }
                if (relu) { v0 = fmaxf(v0, 0.f); v1 = fmaxf(v1, 0.f); }
                if (C) {
                    *reinterpret_cast<float2*>(C + crow + n) = make_float2(v0, v1);
                } else {
                    __nv_bfloat16 h0 = __float2bfloat16(v0);
                    __nv_bfloat16 h1 = __float2bfloat16(v1);
                    __nv_bfloat162 hp = __halves2bfloat162(h0, h1);
                    __nv_bfloat162 lp = __halves2bfloat162(
                        __float2bfloat16(v0 - __bfloat162float(h0)),
                        __float2bfloat16(v1 - __bfloat162float(h1)));
                    *reinterpret_cast<__nv_bfloat162*>(Chi + crow + n) = hp;
                    *reinterpret_cast<__nv_bfloat162*>(Clo + crow + n) = lp;
                }
            }
        }
    }
}

// ---------------- Flash attention (fp32, causal) -> bf16 hi/lo output ------
__global__ void __launch_bounds__(256) attn_kernel(const float* __restrict__ qkv,
                                                   __nv_bfloat16* __restrict__ ohi,
                                                   __nv_bfloat16* __restrict__ olo) {
    __shared__ float Qs[64][65];
    __shared__ float Ks[32][65];
    __shared__ float Vs[32][65];
    __shared__ float Ps[64][33];
    __shared__ float m_s[64], l_s[64], alpha_s[64];

    int tid = threadIdx.x;
    int bh = blockIdx.y;
    int b = bh >> 4, h = bh & 15;
    int qt = blockIdx.x;
    int t0 = qt * 64;
    const float* base = qkv + (size_t)b * TCTX * D3 + h * HDIM;

    for (int i = tid; i < 64 * 64; i += 256) {
        int r = i >> 6, e = i & 63;
        Qs[r][e] = base[(size_t)(t0 + r) * D3 + e];
    }
    if (tid < 64) { m_s[tid] = -1e30f; l_s[tid] = 0.f; }

    int sx = tid & 7, sy = tid >> 3;
    int r0 = sy * 2, c0 = sx * 4;
    int ox = tid & 15, oy = tid >> 4;
    float o[4][4] = {};
    __syncthreads();

    int ntiles = (t0 + 64) / 32;
    for (int kt = 0; kt < ntiles; kt++) {
        int kv0 = kt * 32;
        float oldm[2], oldl[2];
        oldm[0] = m_s[r0];     oldm[1] = m_s[r0 + 1];
        oldl[0] = l_s[r0];     oldl[1] = l_s[r0 + 1];

        for (int i = tid; i < 32 * 64; i += 256) {
            int s = i >> 6, e = i & 63;
            Ks[s][e] = base[(size_t)(kv0 + s) * D3 + DIM + e];
            Vs[s][e] = base[(size_t)(kv0 + s) * D3 + 2 * DIM + e];
        }
        __syncthreads();

        float acc[2][4] = {};
#pragma unroll 8
        for (int k = 0; k < 64; k++) {
            float q0 = Qs[r0][k], q1 = Qs[r0 + 1][k];
#pragma unroll
            for (int j = 0; j < 4; j++) {
                float kv = Ks[c0 + j][k];
                acc[0][j] += q0 * kv;
                acc[1][j] += q1 * kv;
            }
        }
#pragma unroll
        for (int i2 = 0; i2 < 2; i2++) {
            int qg = t0 + r0 + i2;
#pragma unroll
            for (int j = 0; j < 4; j++) {
                int sg = kv0 + c0 + j;
                acc[i2][j] = (sg <= qg) ? acc[i2][j] * 0.125f : -1e30f;
            }
        }
#pragma unroll
        for (int i2 = 0; i2 < 2; i2++) {
            int r = r0 + i2;
            float mx = fmaxf(fmaxf(acc[i2][0], acc[i2][1]), fmaxf(acc[i2][2], acc[i2][3]));
#pragma unroll
            for (int off = 4; off > 0; off >>= 1)
                mx = fmaxf(mx, __shfl_xor_sync(0xffffffffu, mx, off));
            float newm = fmaxf(oldm[i2], mx);
            float p[4], rsum = 0.f;
#pragma unroll
            for (int j = 0; j < 4; j++) {
                p[j] = __expf(acc[i2][j] - newm);
                rsum += p[j];
            }
#pragma unroll
            for (int off = 4; off > 0; off >>= 1)
                rsum += __shfl_xor_sync(0xffffffffu, rsum, off);
            float alpha = __expf(oldm[i2] - newm);
#pragma unroll
            for (int j = 0; j < 4; j++) Ps[r][c0 + j] = p[j];
            if (sx == 0) {
                m_s[r] = newm;
                l_s[r] = alpha * oldl[i2] + rsum;
                alpha_s[r] = alpha;
            }
        }
        __syncthreads();

        float al[4];
#pragma unroll
        for (int i = 0; i < 4; i++) {
            al[i] = alpha_s[oy * 4 + i];
#pragma unroll
            for (int j = 0; j < 4; j++) o[i][j] *= al[i];
        }
#pragma unroll 4
        for (int s = 0; s < 32; s++) {
            float pv[4], vv[4];
#pragma unroll
            for (int i = 0; i < 4; i++) pv[i] = Ps[oy * 4 + i][s];
#pragma unroll
            for (int j = 0; j < 4; j++) vv[j] = Vs[s][ox * 4 + j];
#pragma unroll
            for (int i = 0; i < 4; i++)
#pragma unroll
                for (int j = 0; j < 4; j++)
                    o[i][j] += pv[i] * vv[j];
        }
        __syncthreads();
    }

#pragma unroll
    for (int i = 0; i < 4; i++) {
        int r = oy * 4 + i;
        float inv = 1.0f / l_s[r];
        size_t rowoff = (size_t)(b * TCTX + t0 + r) * DIM + h * HDIM + ox * 4;
#pragma unroll
        for (int j = 0; j < 4; j++) {
            float v = o[i][j] * inv;
            __nv_bfloat16 hh = __float2bfloat16(v);
            ohi[rowoff + j] = hh;
            olo[rowoff + j] = __float2bfloat16(v - __bfloat162float(hh));
        }
    }
}

// ---------------- launch ----------------------------------------------------
extern "C" void kernel_launch(void* const* d_in, const int* in_sizes, int n_in,
                              void* d_out, int out_size) {
    const float* x      = (const float*)d_in[0];
    const float* ln1_w  = (const float*)d_in[1];
    const float* ln1_b  = (const float*)d_in[2];
    const float* wq     = (const float*)d_in[3];
    const float* wk     = (const float*)d_in[4];
    const float* wv     = (const float*)d_in[5];
    const float* w_proj = (const float*)d_in[6];
    const float* b_proj = (const float*)d_in[7];
    const float* ln2_w  = (const float*)d_in[8];
    const float* ln2_b  = (const float*)d_in[9];
    const float* w1     = (const float*)d_in[10];
    const float* b1     = (const float*)d_in[11];
    const float* w2     = (const float*)d_in[12];
    const float* b2     = (const float*)d_in[13];
    float* out = (float*)d_out;

    float *qkv, *x1;
    __nv_bfloat16 *xn_hi, *xn_lo, *at_hi, *at_lo, *xn2_hi, *xn2_lo, *h_hi, *h_lo;
    __nv_bfloat16 *wqkv_hi, *wqkv_lo, *wp_hi, *wp_lo, *w1_hi, *w1_lo, *w2_hi, *w2_lo;
    cudaGetSymbolAddress((void**)&qkv,    g_qkv);
    cudaGetSymbolAddress((void**)&x1,     g_x1);
    cudaGetSymbolAddress((void**)&xn_hi,  g_xn_hi);
    cudaGetSymbolAddress((void**)&xn_lo,  g_xn_lo);
    cudaGetSymbolAddress((void**)&at_hi,  g_at_hi);
    cudaGetSymbolAddress((void**)&at_lo,  g_at_lo);
    cudaGetSymbolAddress((void**)&xn2_hi, g_xn2_hi);
    cudaGetSymbolAddress((void**)&xn2_lo, g_xn2_lo);
    cudaGetSymbolAddress((void**)&h_hi,   g_h_hi);
    cudaGetSymbolAddress((void**)&h_lo,   g_h_lo);
    cudaGetSymbolAddress((void**)&wqkv_hi, g_wqkv_hi);
    cudaGetSymbolAddress((void**)&wqkv_lo, g_wqkv_lo);
    cudaGetSymbolAddress((void**)&wp_hi,  g_wp_hi);
    cudaGetSymbolAddress((void**)&wp_lo,  g_wp_lo);
    cudaGetSymbolAddress((void**)&w1_hi,  g_w1_hi);
    cudaGetSymbolAddress((void**)&w1_lo,  g_w1_lo);
    cudaGetSymbolAddress((void**)&w2_hi,  g_w2_hi);
    cudaGetSymbolAddress((void**)&w2_lo,  g_w2_lo);

    cudaFuncSetAttribute(gemm_mma, cudaFuncAttributeMaxDynamicSharedMemorySize, GSMEM);

    // prep: LN1 + weight repack/transpose/split
    ln_kernel<<<BT_ROWS, 256>>>(x, ln1_w, ln1_b, xn_hi, xn_lo);
    qkv_tsplit_kernel<<<dim3(DIM / 32, D3 / 32), 256>>>(wq, wk, wv, wqkv_hi, wqkv_lo);
    tsplit_kernel<<<dim3(DIM / 32, DIM / 32), 256>>>(w_proj, wp_hi, wp_lo, DIM, DIM);
    tsplit_kernel<<<dim3(D4 / 32, DIM / 32), 256>>>(w1, w1_hi, w1_lo, DIM, D4);
    tsplit_kernel<<<dim3(DIM / 32, D4 / 32), 256>>>(w2, w2_hi, w2_lo, D4, DIM);

    // QKV: [8192,3072] fp32 out
    gemm_mma<<<dim3(D3 / 128, BT_ROWS / 128), 256, GSMEM>>>(
        xn_hi, xn_lo, wqkv_hi, wqkv_lo, qkv, nullptr, nullptr,
        nullptr, nullptr, 0, BT_ROWS, D3, DIM);
    // attention -> bf16 hi/lo
    attn_kernel<<<dim3(TCTX / 64, NB * NH), 256>>>(qkv, at_hi, at_lo);
    // proj + bias + residual(x) -> x1 fp32
    gemm_mma<<<dim3(DIM / 128, BT_ROWS / 128), 256, GSMEM>>>(
        at_hi, at_lo, wp_hi, wp_lo, x1, nullptr, nullptr,
        b_proj, x, 0, BT_ROWS, DIM, DIM);
    // LN2 -> bf16 hi/lo
    ln_kernel<<<BT_ROWS, 256>>>(x1, ln2_w, ln2_b, xn2_hi, xn2_lo);
    // MLP up + bias + relu -> h bf16 hi/lo
    gemm_mma<<<dim3(D4 / 128, BT_ROWS / 128), 256, GSMEM>>>(
        xn2_hi, xn2_lo, w1_hi, w1_lo, nullptr, h_hi, h_lo,
        b1, nullptr, 1, BT_ROWS, D4, DIM);
    // MLP down + bias + residual(x1) -> out fp32
    gemm_mma<<<dim3(DIM / 128, BT_ROWS / 128), 256, GSMEM>>>(
        h_hi, h_lo, w2_hi, w2_lo, out, nullptr, nullptr,
        b2, x1, 0, BT_ROWS, DIM, D4);
}

// round 4
// speedup vs baseline: 3.0699x; 1.5022x over previous
#include <cuda_runtime.h>
#include <cuda_bf16.h>
#include <cstdint>
#include <math.h>

#define BT_ROWS 8192   // B*T
#define DIM     1024
#define NH      16
#define HDIM    64
#define TCTX    2048
#define NB      4
#define D3      3072
#define D4      4096

// ---------------- scratch (device globals) ---------------------------------
__device__ float g_x1 [BT_ROWS * DIM];    // x after attn residual (fp32)
__device__ __nv_bfloat16 g_qkv_hi[(size_t)BT_ROWS * D3], g_qkv_lo[(size_t)BT_ROWS * D3];
__device__ __nv_bfloat16 g_xn_hi [BT_ROWS * DIM], g_xn_lo [BT_ROWS * DIM];
__device__ __nv_bfloat16 g_at_hi [BT_ROWS * DIM], g_at_lo [BT_ROWS * DIM];
__device__ __nv_bfloat16 g_xn2_hi[BT_ROWS * DIM], g_xn2_lo[BT_ROWS * DIM];
__device__ __nv_bfloat16 g_h_hi  [(size_t)BT_ROWS * D4], g_h_lo[(size_t)BT_ROWS * D4];
__device__ __nv_bfloat16 g_wqkv_hi[D3 * DIM], g_wqkv_lo[D3 * DIM];   // [N=3072, K=1024]
__device__ __nv_bfloat16 g_wp_hi [DIM * DIM], g_wp_lo [DIM * DIM];   // [N=1024, K=1024]
__device__ __nv_bfloat16 g_w1_hi [D4 * DIM],  g_w1_lo [D4 * DIM];    // [N=4096, K=1024]
__device__ __nv_bfloat16 g_w2_hi [DIM * D4],  g_w2_lo [DIM * D4];    // [N=1024, K=4096]

// ---------------- PTX helpers (sm_80-era ISA only; no tcgen05) -------------
__device__ __forceinline__ uint32_t smem_u32(const void* p) {
    return (uint32_t)__cvta_generic_to_shared(p);
}
__device__ __forceinline__ void ldgsts16(uint32_t s, const void* g) {
    asm volatile("cp.async.cg.shared.global [%0], [%1], 16;" :: "r"(s), "l"(g));
}
__device__ __forceinline__ void cp_commit() {
    asm volatile("cp.async.commit_group;" ::: "memory");
}
__device__ __forceinline__ void cp_wait1() {
    asm volatile("cp.async.wait_group 1;" ::: "memory");
}
__device__ __forceinline__ void ldm_x4(uint32_t* r, uint32_t addr) {
    asm volatile("ldmatrix.sync.aligned.m8n8.x4.shared.b16 {%0,%1,%2,%3}, [%4];"
                 : "=r"(r[0]), "=r"(r[1]), "=r"(r[2]), "=r"(r[3]) : "r"(addr));
}
__device__ __forceinline__ void ldm_x2(uint32_t* r, uint32_t addr) {
    asm volatile("ldmatrix.sync.aligned.m8n8.x2.shared.b16 {%0,%1}, [%2];"
                 : "=r"(r[0]), "=r"(r[1]) : "r"(addr));
}
__device__ __forceinline__ void ldm_x4t(uint32_t* r, uint32_t addr) {
    asm volatile("ldmatrix.sync.aligned.m8n8.x4.trans.shared.b16 {%0,%1,%2,%3}, [%4];"
                 : "=r"(r[0]), "=r"(r[1]), "=r"(r[2]), "=r"(r[3]) : "r"(addr));
}
__device__ __forceinline__ void mma16816(float* d, const uint32_t* a, const uint32_t* b) {
    asm volatile("mma.sync.aligned.m16n8k16.row.col.f32.bf16.bf16.f32 "
                 "{%0,%1,%2,%3}, {%4,%5,%6,%7}, {%8,%9}, {%0,%1,%2,%3};"
                 : "+f"(d[0]), "+f"(d[1]), "+f"(d[2]), "+f"(d[3])
                 : "r"(a[0]), "r"(a[1]), "r"(a[2]), "r"(a[3]), "r"(b[0]), "r"(b[1]));
}
__device__ __forceinline__ void split2(float a, float b, uint32_t& hi, uint32_t& lo) {
    __nv_bfloat16 ah = __float2bfloat16(a), bh = __float2bfloat16(b);
    __nv_bfloat16 al = __float2bfloat16(a - __bfloat162float(ah));
    __nv_bfloat16 bl = __float2bfloat16(b - __bfloat162float(bh));
    __nv_bfloat162 h2 = __halves2bfloat162(ah, bh), l2 = __halves2bfloat162(al, bl);
    hi = *reinterpret_cast<uint32_t*>(&h2);
    lo = *reinterpret_cast<uint32_t*>(&l2);
}

// ---------------- LayerNorm -> bf16 hi/lo split ----------------------------
__global__ void __launch_bounds__(256) ln_kernel(const float* __restrict__ x,
                                                 const float* __restrict__ w,
                                                 const float* __restrict__ b,
                                                 __nv_bfloat16* __restrict__ ohi,
                                                 __nv_bfloat16* __restrict__ olo) {
    int row = blockIdx.x;
    int tid = threadIdx.x;
    const float4* xr = reinterpret_cast<const float4*>(x + (size_t)row * DIM);
    float4 v = xr[tid];
    float s  = v.x + v.y + v.z + v.w;
    float ss = v.x * v.x + v.y * v.y + v.z * v.z + v.w * v.w;
#pragma unroll
    for (int off = 16; off > 0; off >>= 1) {
        s  += __shfl_xor_sync(0xffffffffu, s,  off);
        ss += __shfl_xor_sync(0xffffffffu, ss, off);
    }
    __shared__ float sm[8], sm2[8];
    __shared__ float mu_sh, rstd_sh;
    int wid = tid >> 5, lane = tid & 31;
    if (lane == 0) { sm[wid] = s; sm2[wid] = ss; }
    __syncthreads();
    if (tid == 0) {
        float ts = 0.f, tss = 0.f;
#pragma unroll
        for (int i = 0; i < 8; i++) { ts += sm[i]; tss += sm2[i]; }
        float mu  = ts * (1.0f / DIM);
        float var = tss * (1.0f / DIM) - mu * mu;
        mu_sh   = mu;
        rstd_sh = rsqrtf(var + 1e-5f);
    }
    __syncthreads();
    float mu = mu_sh, rstd = rstd_sh;
    float4 wv = reinterpret_cast<const float4*>(w)[tid];
    float4 bv = reinterpret_cast<const float4*>(b)[tid];
    float o[4];
    o[0] = (v.x - mu) * rstd * wv.x + bv.x;
    o[1] = (v.y - mu) * rstd * wv.y + bv.y;
    o[2] = (v.z - mu) * rstd * wv.z + bv.z;
    o[3] = (v.w - mu) * rstd * wv.w + bv.w;
    __nv_bfloat16 hh[4], ll[4];
#pragma unroll
    for (int j = 0; j < 4; j++) {
        hh[j] = __float2bfloat16(o[j]);
        ll[j] = __float2bfloat16(o[j] - __bfloat162float(hh[j]));
    }
    size_t base = (size_t)row * DIM + tid * 4;
    *reinterpret_cast<uint2*>(ohi + base) = *reinterpret_cast<uint2*>(hh);
    *reinterpret_cast<uint2*>(olo + base) = *reinterpret_cast<uint2*>(ll);
}

// ---------------- weight transpose + split: [R,C] fp32 -> [C,R] bf16 hi/lo --
__global__ void __launch_bounds__(256) tsplit_kernel(const float* __restrict__ src,
                                                     __nv_bfloat16* __restrict__ dhi,
                                                     __nv_bfloat16* __restrict__ dlo,
                                                     int R, int C) {
    __shared__ float t[32][33];
    int c0 = blockIdx.x * 32, r0 = blockIdx.y * 32;
    int x = threadIdx.x & 31, y = threadIdx.x >> 5;
#pragma unroll
    for (int i = 0; i < 32; i += 8)
        t[y + i][x] = src[(size_t)(r0 + y + i) * C + c0 + x];
    __syncthreads();
#pragma unroll
    for (int i = 0; i < 32; i += 8) {
        float v = t[x][y + i];
        size_t o = (size_t)(c0 + y + i) * R + r0 + x;
        __nv_bfloat16 hh = __float2bfloat16(v);
        dhi[o] = hh;
        dlo[o] = __float2bfloat16(v - __bfloat162float(hh));
    }
}

// ---------------- qkv weights [H,D,HD]x3 -> [3072, 1024] bf16 hi/lo --------
__global__ void __launch_bounds__(256) qkv_tsplit_kernel(const float* __restrict__ wq,
                                                         const float* __restrict__ wk,
                                                         const float* __restrict__ wv,
                                                         __nv_bfloat16* __restrict__ dhi,
                                                         __nv_bfloat16* __restrict__ dlo) {
    __shared__ float t[32][33];
    int k0 = blockIdx.x * 32;
    int n0 = blockIdx.y * 32;
    int m = n0 >> 10, h = (n0 >> 6) & 15, e0 = n0 & 63;
    const float* src = (m == 0) ? wq : (m == 1) ? wk : wv;
    int x = threadIdx.x & 31, y = threadIdx.x >> 5;
#pragma unroll
    for (int j = 0; j < 32; j += 8)
        t[y + j][x] = src[((size_t)h * DIM + k0 + y + j) * HDIM + e0 + x];
    __syncthreads();
#pragma unroll
    for (int i = 0; i < 32; i += 8) {
        float v = t[x][y + i];           // src[h][k0+x][e0+y+i]
        size_t o = (size_t)(n0 + y + i) * DIM + k0 + x;
        __nv_bfloat16 hh = __float2bfloat16(v);
        dhi[o] = hh;
        dlo[o] = __float2bfloat16(v - __bfloat162float(hh));
    }
}

// ---------------- MMA GEMM: C[M,N] = A[M,K] @ B[N,K]^T ---------------------
// bf16x3 split (AhiBhi + AloBhi + AhiBlo), fp32 accum via mma.m16n8k16.
// 128x128x32 CTA tile, 8 warps (2x4), warp tile 64x32, 3-stage cp.async.
#define PADB    80      // padded row stride in bytes (32 bf16 + 8 pad)
#define TILE_B  (128 * PADB)            // 10240 B per tile
#define STAGE_B (4 * TILE_B)            // Ahi|Alo|Bhi|Blo = 40960 B
#define NSTAGE  3
#define GSMEM   (NSTAGE * STAGE_B)      // 122880 B

__device__ __forceinline__ void stage_load(uint32_t sbase,
                                           const __nv_bfloat16* __restrict__ Ahi,
                                           const __nv_bfloat16* __restrict__ Alo,
                                           const __nv_bfloat16* __restrict__ Bhi,
                                           const __nv_bfloat16* __restrict__ Blo,
                                           int bm, int bn, int k0, int K, int tid) {
#pragma unroll
    for (int p = 0; p < 2; p++) {
        int idx = tid + (p << 8);
        int row = idx >> 2;
        int c16 = idx & 3;
        uint32_t soff = (uint32_t)row * PADB + (c16 << 4);
        size_t ga = (size_t)(bm + row) * K + k0 + (c16 << 3);
        size_t gb = (size_t)(bn + row) * K + k0 + (c16 << 3);
        ldgsts16(sbase + soff,              Ahi + ga);
        ldgsts16(sbase + TILE_B + soff,     Alo + ga);
        ldgsts16(sbase + 2 * TILE_B + soff, Bhi + gb);
        ldgsts16(sbase + 3 * TILE_B + soff, Blo + gb);
    }
}

__global__ void __launch_bounds__(256, 1) gemm_mma(
    const __nv_bfloat16* __restrict__ Ahi, const __nv_bfloat16* __restrict__ Alo,
    const __nv_bfloat16* __restrict__ Bhi, const __nv_bfloat16* __restrict__ Blo,
    float* __restrict__ C, __nv_bfloat16* __restrict__ Chi, __nv_bfloat16* __restrict__ Clo,
    const float* __restrict__ bias, const float* __restrict__ res, int relu,
    int M, int N, int K) {
    extern __shared__ char dsm[];
    int tid  = threadIdx.x;
    int wid  = tid >> 5;
    int lane = tid & 31;
    int bm = blockIdx.y * 128, bn = blockIdx.x * 128;
    int wm = (wid >> 2) * 64;      // warp row offset in tile
    int wn = (wid & 3) * 32;       // warp col offset in tile

    uint32_t sb = smem_u32(dsm);
    const int KT = K >> 5;         // k-tiles of 32

    float acc[4][4][4] = {};       // [mi][ni][reg]

    // prologue: stages 0..NSTAGE-2
#pragma unroll
    for (int s = 0; s < NSTAGE - 1; s++) {
        stage_load(sb + s * STAGE_B, Ahi, Alo, Bhi, Blo, bm, bn, s << 5, K, tid);
        cp_commit();
    }
    cp_wait1();
    __syncthreads();

    // ldmatrix per-lane address components
    int arow = lane & 15;
    int acolb = (lane >> 4) << 4;              // (lane/16)*8 elems * 2B
    int brow = lane & 7;
    int bcolb = ((lane >> 3) & 1) << 4;

    for (int kt = 0; kt < KT; kt++) {
        uint32_t st = sb + (uint32_t)(kt % NSTAGE) * STAGE_B;
#pragma unroll
        for (int ks = 0; ks < 2; ks++) {
            int kb = ks << 5;                  // 16 elems = 32 bytes
            uint32_t ahi[4][4], alo[4][4], bhi[4][2], blo[4][2];
#pragma unroll
            for (int mi = 0; mi < 4; mi++) {
                uint32_t ra = st + (uint32_t)(wm + mi * 16 + arow) * PADB + kb + acolb;
                ldm_x4(ahi[mi], ra);
                ldm_x4(alo[mi], ra + TILE_B);
            }
#pragma unroll
            for (int ni = 0; ni < 4; ni++) {
                uint32_t rb = st + 2 * TILE_B + (uint32_t)(wn + ni * 8 + brow) * PADB + kb + bcolb;
                ldm_x2(bhi[ni], rb);
                ldm_x2(blo[ni], rb + TILE_B);
            }
#pragma unroll
            for (int mi = 0; mi < 4; mi++)
#pragma unroll
                for (int ni = 0; ni < 4; ni++) {
                    mma16816(acc[mi][ni], ahi[mi], bhi[ni]);
                    mma16816(acc[mi][ni], alo[mi], bhi[ni]);
                    mma16816(acc[mi][ni], ahi[mi], blo[ni]);
                }
        }
        // issue next stage (slot was consumed at iteration kt-1; all warps
        // passed the trailing __syncthreads since then)
        int ktn = kt + NSTAGE - 1;
        if (ktn < KT)
            stage_load(sb + (uint32_t)(ktn % NSTAGE) * STAGE_B,
                       Ahi, Alo, Bhi, Blo, bm, bn, ktn << 5, K, tid);
        cp_commit();   // empty group in tail keeps wait semantics uniform
        cp_wait1();
        __syncthreads();
    }

    // epilogue
    int gr = lane >> 2;
    int gc = (lane & 3) << 1;
#pragma unroll
    for (int mi = 0; mi < 4; mi++) {
#pragma unroll
        for (int rr = 0; rr < 2; rr++) {
            int m = bm + wm + mi * 16 + rr * 8 + gr;
            size_t crow = (size_t)m * N;
#pragma unroll
            for (int ni = 0; ni < 4; ni++) {
                int n = bn + wn + ni * 8 + gc;
                float v0 = acc[mi][ni][rr * 2 + 0];
                float v1 = acc[mi][ni][rr * 2 + 1];
                if (bias) {
                    float2 bv = *reinterpret_cast<const float2*>(bias + n);
                    v0 += bv.x; v1 += bv.y;
                }
                if (res) {
                    float2 rv = *reinterpret_cast<const float2*>(res + crow + n);
                    v0 += rv.x; v1 += rv.y;
                }
                if (relu) { v0 = fmaxf(v0, 0.f); v1 = fmaxf(v1, 0.f); }
                if (C) {
                    *reinterpret_cast<float2*>(C + crow + n) = make_float2(v0, v1);
                } else {
                    uint32_t hp, lp;
                    split2(v0, v1, hp, lp);
                    *reinterpret_cast<uint32_t*>(Chi + crow + n) = hp;
                    *reinterpret_cast<uint32_t*>(Clo + crow + n) = lp;
                }
            }
        }
    }
}

// ---------------- Tensor-core flash attention (bf16x3, causal) -------------
// BQ=128, BKV=64, 8 warps; warp = 16 q-rows x 64 kv. Double-buffered K/V.
#define AQ      128
#define AKV     64
#define APADE   72                  // row stride in bf16 elems
#define AROWB   (APADE * 2)         // 144 B
#define QTILE_B (AQ * AROWB)        // 18432
#define KTILE_B (AKV * AROWB)       // 9216
#define ASTAGE_B (4 * KTILE_B)      // Khi|Klo|Vhi|Vlo = 36864
#define ASMEM   (2 * QTILE_B + 2 * ASTAGE_B)   // 110592

__global__ void __launch_bounds__(256, 1) attn_mma(
    const __nv_bfloat16* __restrict__ qkv_hi,
    const __nv_bfloat16* __restrict__ qkv_lo,
    __nv_bfloat16* __restrict__ out_hi,
    __nv_bfloat16* __restrict__ out_lo) {
    extern __shared__ char dsm[];
    int tid  = threadIdx.x;
    int wid  = tid >> 5;
    int lane = tid & 31;
    int bh = blockIdx.y;
    int b = bh >> 4, h = bh & 15;
    int t0 = blockIdx.x * AQ;
    int wm = wid << 4;              // warp q-row offset (16 rows per warp)

    uint32_t sb   = smem_u32(dsm);
    uint32_t sQhi = sb;
    uint32_t sQlo = sb + QTILE_B;
    uint32_t sKV  = sb + 2 * QTILE_B;

    const size_t qoff = ((size_t)b * TCTX + t0) * D3 + (size_t)h * HDIM;

    // ---- prologue loads ----
    // Q tile: 128 rows x 64 bf16, hi+lo
#pragma unroll
    for (int p = 0; p < 4; p++) {
        int idx = tid + (p << 8);
        int row = idx >> 3;
        uint32_t cb = (uint32_t)(idx & 7) << 4;    // byte col
        uint32_t so = (uint32_t)row * AROWB + cb;
        size_t go = qoff + (size_t)row * D3 + (cb >> 1);
        ldgsts16(sQhi + so, qkv_hi + go);
        ldgsts16(sQlo + so, qkv_lo + go);
    }
    const int nt = (t0 >> 6) + 2;   // kv tiles of 64

    // K/V stage loader
    auto load_stage = [&](int kt) {
        uint32_t st = sKV + (uint32_t)(kt & 1) * ASTAGE_B;
        size_t kv0 = (size_t)kt * AKV;
        size_t koff = ((size_t)b * TCTX + kv0) * D3 + DIM + (size_t)h * HDIM;
        size_t voff = koff + DIM;
#pragma unroll
        for (int p = 0; p < 2; p++) {
            int idx = tid + (p << 8);
            int row = idx >> 3;
            uint32_t cb = (uint32_t)(idx & 7) << 4;
            uint32_t so = (uint32_t)row * AROWB + cb;
            size_t gk = koff + (size_t)row * D3 + (cb >> 1);
            size_t gv = voff + (size_t)row * D3 + (cb >> 1);
            ldgsts16(st + so,               qkv_hi + gk);
            ldgsts16(st + KTILE_B + so,     qkv_lo + gk);
            ldgsts16(st + 2 * KTILE_B + so, qkv_hi + gv);
            ldgsts16(st + 3 * KTILE_B + so, qkv_lo + gv);
        }
    };
    load_stage(0);
    cp_commit();                   // G0: Q + stage0
    if (nt > 1) load_stage(1);
    cp_commit();                   // G1

    // per-thread state
    float o[8][4] = {};
    float m0 = -1e30f, m1 = -1e30f, l0 = 0.f, l1 = 0.f;
    uint32_t qhi[4][4], qlo[4][4];

    // fragment address components
    int arow  = lane & 15;
    int acolb = (lane >> 4) << 4;
    int krow  = (lane & 7) + ((lane >> 4) << 3);
    int kcolb = ((lane >> 3) & 1) << 4;
    int vrow  = (lane & 7) + (((lane >> 3) & 1) << 3);
    int vcole = (lane >> 4) << 3;   // elems

    for (int kt = 0; kt < nt; kt++) {
        cp_wait1();
        __syncthreads();
        if (kt == 0) {
            // load Q fragments once
#pragma unroll
            for (int kk = 0; kk < 4; kk++) {
                uint32_t qa = (uint32_t)(wm + arow) * AROWB + (kk << 5) + acolb;
                ldm_x4(qhi[kk], sQhi + qa);
                ldm_x4(qlo[kk], sQlo + qa);
            }
        }
        uint32_t st = sKV + (uint32_t)(kt & 1) * ASTAGE_B;
        int kv0 = kt << 6;

        // ---- S = Q K^T (bf16x3) ----
        float s[8][4] = {};
#pragma unroll
        for (int kk = 0; kk < 4; kk++) {
#pragma unroll
            for (int np = 0; np < 4; np++) {
                uint32_t ka = st + (uint32_t)(np * 16 + krow) * AROWB + (kk << 5) + kcolb;
                uint32_t kh[4], kl[4];
                ldm_x4(kh, ka);
                ldm_x4(kl, ka + KTILE_B);
                mma16816(s[2 * np],     qhi[kk], kh);
                mma16816(s[2 * np],     qlo[kk], kh);
                mma16816(s[2 * np],     qhi[kk], kl);
                mma16816(s[2 * np + 1], qhi[kk], kh + 2);
                mma16816(s[2 * np + 1], qlo[kk], kh + 2);
                mma16816(s[2 * np + 1], qhi[kk], kl + 2);
            }
        }

        // ---- scale + causal mask ----
        int rbase = t0 + wm + (lane >> 2);
        bool need_mask = (kv0 + AKV - 1) > (t0 + wm);
#pragma unroll
        for (int ni = 0; ni < 8; ni++) {
#pragma unroll
            for (int j = 0; j < 4; j++) {
                s[ni][j] *= 0.125f;
                if (need_mask) {
                    int col = kv0 + ni * 8 + ((lane & 3) << 1) + (j & 1);
                    int row = rbase + ((j >> 1) << 3);
                    if (col > row) s[ni][j] = -1e30f;
                }
            }
        }

        // ---- online softmax (rows r and r+8, warp-local) ----
        float mx0 = -1e30f, mx1 = -1e30f;
#pragma unroll
        for (int ni = 0; ni < 8; ni++) {
            mx0 = fmaxf(mx0, fmaxf(s[ni][0], s[ni][1]));
            mx1 = fmaxf(mx1, fmaxf(s[ni][2], s[ni][3]));
        }
#pragma unroll
        for (int off = 1; off < 4; off <<= 1) {
            mx0 = fmaxf(mx0, __shfl_xor_sync(0xffffffffu, mx0, off));
            mx1 = fmaxf(mx1, __shfl_xor_sync(0xffffffffu, mx1, off));
        }
        float nm0 = fmaxf(m0, mx0), nm1 = fmaxf(m1, mx1);
        float a0 = __expf(m0 - nm0), a1 = __expf(m1 - nm1);
        m0 = nm0; m1 = nm1;
        float rs0 = 0.f, rs1 = 0.f;
#pragma unroll
        for (int ni = 0; ni < 8; ni++) {
            s[ni][0] = __expf(s[ni][0] - nm0);
            s[ni][1] = __expf(s[ni][1] - nm0);
            s[ni][2] = __expf(s[ni][2] - nm1);
            s[ni][3] = __expf(s[ni][3] - nm1);
            rs0 += s[ni][0] + s[ni][1];
            rs1 += s[ni][2] + s[ni][3];
        }
#pragma unroll
        for (int off = 1; off < 4; off <<= 1) {
            rs0 += __shfl_xor_sync(0xffffffffu, rs0, off);
            rs1 += __shfl_xor_sync(0xffffffffu, rs1, off);
        }
        l0 = a0 * l0 + rs0;
        l1 = a1 * l1 + rs1;
#pragma unroll
        for (int ni = 0; ni < 8; ni++) {
            o[ni][0] *= a0; o[ni][1] *= a0;
            o[ni][2] *= a1; o[ni][3] *= a1;
        }

        // ---- O += P V (bf16x3; P from registers, V via ldmatrix.trans) ----
        uint32_t sVhi = st + 2 * KTILE_B;
#pragma unroll
        for (int kk2 = 0; kk2 < 4; kk2++) {
            uint32_t phi[4], plo[4];
            split2(s[2 * kk2][0],     s[2 * kk2][1],     phi[0], plo[0]);
            split2(s[2 * kk2][2],     s[2 * kk2][3],     phi[1], plo[1]);
            split2(s[2 * kk2 + 1][0], s[2 * kk2 + 1][1], phi[2], plo[2]);
            split2(s[2 * kk2 + 1][2], s[2 * kk2 + 1][3], phi[3], plo[3]);
#pragma unroll
            for (int np = 0; np < 4; np++) {
                uint32_t va = sVhi + (uint32_t)(kk2 * 16 + vrow) * AROWB
                            + (uint32_t)(np * 16 + vcole) * 2;
                uint32_t vh[4], vl[4];
                ldm_x4t(vh, va);
                ldm_x4t(vl, va + KTILE_B);
                mma16816(o[2 * np],     phi, vh);
                mma16816(o[2 * np],     plo, vh);
                mma16816(o[2 * np],     phi, vl);
                mma16816(o[2 * np + 1], phi, vh + 2);
                mma16816(o[2 * np + 1], plo, vh + 2);
                mma16816(o[2 * np + 1], phi, vl + 2);
            }
        }
        __syncthreads();
        if (kt + 2 < nt) load_stage(kt + 2);
        cp_commit();
    }

    // ---- normalize + write bf16 hi/lo ----
    float inv0 = 1.0f / l0, inv1 = 1.0f / l1;
    int r0g = t0 + wm + (lane >> 2);
    size_t base0 = ((size_t)b * TCTX + r0g) * DIM + (size_t)h * HDIM + ((lane & 3) << 1);
    size_t base1 = base0 + 8 * DIM;
#pragma unroll
    for (int ni = 0; ni < 8; ni++) {
        uint32_t hp, lp;
        split2(o[ni][0] * inv0, o[ni][1] * inv0, hp, lp);
        *reinterpret_cast<uint32_t*>(out_hi + base0 + ni * 8) = hp;
        *reinterpret_cast<uint32_t*>(out_lo + base0 + ni * 8) = lp;
        split2(o[ni][2] * inv1, o[ni][3] * inv1, hp, lp);
        *reinterpret_cast<uint32_t*>(out_hi + base1 + ni * 8) = hp;
        *reinterpret_cast<uint32_t*>(out_lo + base1 + ni * 8) = lp;
    }
}

// ---------------- launch ----------------------------------------------------
extern "C" void kernel_launch(void* const* d_in, const int* in_sizes, int n_in,
                              void* d_out, int out_size) {
    const float* x      = (const float*)d_in[0];
    const float* ln1_w  = (const float*)d_in[1];
    const float* ln1_b  = (const float*)d_in[2];
    const float* wq     = (const float*)d_in[3];
    const float* wk     = (const float*)d_in[4];
    const float* wv     = (const float*)d_in[5];
    const float* w_proj = (const float*)d_in[6];
    const float* b_proj = (const float*)d_in[7];
    const float* ln2_w  = (const float*)d_in[8];
    const float* ln2_b  = (const float*)d_in[9];
    const float* w1     = (const float*)d_in[10];
    const float* b1     = (const float*)d_in[11];
    const float* w2     = (const float*)d_in[12];
    const float* b2     = (const float*)d_in[13];
    float* out = (float*)d_out;

    float *x1;
    __nv_bfloat16 *qkv_hi, *qkv_lo;
    __nv_bfloat16 *xn_hi, *xn_lo, *at_hi, *at_lo, *xn2_hi, *xn2_lo, *h_hi, *h_lo;
    __nv_bfloat16 *wqkv_hi, *wqkv_lo, *wp_hi, *wp_lo, *w1_hi, *w1_lo, *w2_hi, *w2_lo;
    cudaGetSymbolAddress((void**)&x1,     g_x1);
    cudaGetSymbolAddress((void**)&qkv_hi, g_qkv_hi);
    cudaGetSymbolAddress((void**)&qkv_lo, g_qkv_lo);
    cudaGetSymbolAddress((void**)&xn_hi,  g_xn_hi);
    cudaGetSymbolAddress((void**)&xn_lo,  g_xn_lo);
    cudaGetSymbolAddress((void**)&at_hi,  g_at_hi);
    cudaGetSymbolAddress((void**)&at_lo,  g_at_lo);
    cudaGetSymbolAddress((void**)&xn2_hi, g_xn2_hi);
    cudaGetSymbolAddress((void**)&xn2_lo, g_xn2_lo);
    cudaGetSymbolAddress((void**)&h_hi,   g_h_hi);
    cudaGetSymbolAddress((void**)&h_lo,   g_h_lo);
    cudaGetSymbolAddress((void**)&wqkv_hi, g_wqkv_hi);
    cudaGetSymbolAddress((void**)&wqkv_lo, g_wqkv_lo);
    cudaGetSymbolAddress((void**)&wp_hi,  g_wp_hi);
    cudaGetSymbolAddress((void**)&wp_lo,  g_wp_lo);
    cudaGetSymbolAddress((void**)&w1_hi,  g_w1_hi);
    cudaGetSymbolAddress((void**)&w1_lo,  g_w1_lo);
    cudaGetSymbolAddress((void**)&w2_hi,  g_w2_hi);
    cudaGetSymbolAddress((void**)&w2_lo,  g_w2_lo);

    cudaFuncSetAttribute(gemm_mma, cudaFuncAttributeMaxDynamicSharedMemorySize, GSMEM);
    cudaFuncSetAttribute(attn_mma, cudaFuncAttributeMaxDynamicSharedMemorySize, ASMEM);

    // prep: LN1 + weight repack/transpose/split
    ln_kernel<<<BT_ROWS, 256>>>(x, ln1_w, ln1_b, xn_hi, xn_lo);
    qkv_tsplit_kernel<<<dim3(DIM / 32, D3 / 32), 256>>>(wq, wk, wv, wqkv_hi, wqkv_lo);
    tsplit_kernel<<<dim3(DIM / 32, DIM / 32), 256>>>(w_proj, wp_hi, wp_lo, DIM, DIM);
    tsplit_kernel<<<dim3(D4 / 32, DIM / 32), 256>>>(w1, w1_hi, w1_lo, DIM, D4);
    tsplit_kernel<<<dim3(DIM / 32, D4 / 32), 256>>>(w2, w2_hi, w2_lo, D4, DIM);

    // QKV: [8192,3072] -> bf16 hi/lo
    gemm_mma<<<dim3(D3 / 128, BT_ROWS / 128), 256, GSMEM>>>(
        xn_hi, xn_lo, wqkv_hi, wqkv_lo, nullptr, qkv_hi, qkv_lo,
        nullptr, nullptr, 0, BT_ROWS, D3, DIM);
    // tensor-core flash attention -> bf16 hi/lo
    attn_mma<<<dim3(TCTX / AQ, NB * NH), 256, ASMEM>>>(qkv_hi, qkv_lo, at_hi, at_lo);
    // proj + bias + residual(x) -> x1 fp32
    gemm_mma<<<dim3(DIM / 128, BT_ROWS / 128), 256, GSMEM>>>(
        at_hi, at_lo, wp_hi, wp_lo, x1, nullptr, nullptr,
        b_proj, x, 0, BT_ROWS, DIM, DIM);
    // LN2 -> bf16 hi/lo
    ln_kernel<<<BT_ROWS, 256>>>(x1, ln2_w, ln2_b, xn2_hi, xn2_lo);
    // MLP up + bias + relu -> h bf16 hi/lo
    gemm_mma<<<dim3(D4 / 128, BT_ROWS / 128), 256, GSMEM>>>(
        xn2_hi, xn2_lo, w1_hi, w1_lo, nullptr, h_hi, h_lo,
        b1, nullptr, 1, BT_ROWS, D4, DIM);
    // MLP down + bias + residual(x1) -> out fp32
    gemm_mma<<<dim3(DIM / 128, BT_ROWS / 128), 256, GSMEM>>>(
        h_hi, h_lo, w2_hi, w2_lo, out, nullptr, nullptr,
        b2, x1, 0, BT_ROWS, DIM, D4);
}

// round 5
// speedup vs baseline: 4.7978x; 1.5629x over previous
#include <cuda_runtime.h>
#include <cuda_fp16.h>
#include <cstdint>
#include <math.h>

#define BT_ROWS 8192   // B*T
#define DIM     1024
#define NH      16
#define HDIM    64
#define TCTX    2048
#define NB      4
#define D3      3072
#define D4      4096

// ---------------- scratch (device globals) ---------------------------------
__device__ float g_x1 [BT_ROWS * DIM];    // x after attn residual (fp32)
__device__ __half g_qkv_hi[(size_t)BT_ROWS * D3], g_qkv_lo[(size_t)BT_ROWS * D3];
__device__ __half g_xn_hi [BT_ROWS * DIM], g_xn_lo [BT_ROWS * DIM];
__device__ __half g_at_hi [BT_ROWS * DIM], g_at_lo [BT_ROWS * DIM];
__device__ __half g_xn2_hi[BT_ROWS * DIM], g_xn2_lo[BT_ROWS * DIM];
__device__ __half g_h_hi  [(size_t)BT_ROWS * D4], g_h_lo[(size_t)BT_ROWS * D4];
__device__ __half g_wqkv[D3 * DIM];   // [N=3072, K=1024] fp16 (hi only)
__device__ __half g_wp  [DIM * DIM];
__device__ __half g_w1  [D4 * DIM];
__device__ __half g_w2  [DIM * D4];

// ---------------- PTX helpers (sm_80-era ISA only; no tcgen05) -------------
__device__ __forceinline__ uint32_t smem_u32(const void* p) {
    return (uint32_t)__cvta_generic_to_shared(p);
}
__device__ __forceinline__ void ldgsts16(uint32_t s, const void* g) {
    asm volatile("cp.async.cg.shared.global [%0], [%1], 16;" :: "r"(s), "l"(g));
}
__device__ __forceinline__ void cp_commit() {
    asm volatile("cp.async.commit_group;" ::: "memory");
}
__device__ __forceinline__ void cp_wait1() {
    asm volatile("cp.async.wait_group 1;" ::: "memory");
}
__device__ __forceinline__ void ldm_x4(uint32_t* r, uint32_t addr) {
    asm volatile("ldmatrix.sync.aligned.m8n8.x4.shared.b16 {%0,%1,%2,%3}, [%4];"
                 : "=r"(r[0]), "=r"(r[1]), "=r"(r[2]), "=r"(r[3]) : "r"(addr));
}
__device__ __forceinline__ void ldm_x2(uint32_t* r, uint32_t addr) {
    asm volatile("ldmatrix.sync.aligned.m8n8.x2.shared.b16 {%0,%1}, [%2];"
                 : "=r"(r[0]), "=r"(r[1]) : "r"(addr));
}
__device__ __forceinline__ void ldm_x4t(uint32_t* r, uint32_t addr) {
    asm volatile("ldmatrix.sync.aligned.m8n8.x4.trans.shared.b16 {%0,%1,%2,%3}, [%4];"
                 : "=r"(r[0]), "=r"(r[1]), "=r"(r[2]), "=r"(r[3]) : "r"(addr));
}
__device__ __forceinline__ void mma16816(float* d, const uint32_t* a, const uint32_t* b) {
    asm volatile("mma.sync.aligned.m16n8k16.row.col.f32.f16.f16.f32 "
                 "{%0,%1,%2,%3}, {%4,%5,%6,%7}, {%8,%9}, {%0,%1,%2,%3};"
                 : "+f"(d[0]), "+f"(d[1]), "+f"(d[2]), "+f"(d[3])
                 : "r"(a[0]), "r"(a[1]), "r"(a[2]), "r"(a[3]), "r"(b[0]), "r"(b[1]));
}
__device__ __forceinline__ void split2h(float a, float b, uint32_t& hi, uint32_t& lo) {
    __half ah = __float2half_rn(a), bh = __float2half_rn(b);
    __half al = __float2half_rn(a - __half2float(ah));
    __half bl = __float2half_rn(b - __half2float(bh));
    __half2 h2 = __halves2half2(ah, bh), l2 = __halves2half2(al, bl);
    hi = *reinterpret_cast<uint32_t*>(&h2);
    lo = *reinterpret_cast<uint32_t*>(&l2);
}

// ---------------- LayerNorm -> fp16 hi/lo split -----------------------------
__global__ void __launch_bounds__(256) ln_kernel(const float* __restrict__ x,
                                                 const float* __restrict__ w,
                                                 const float* __restrict__ b,
                                                 __half* __restrict__ ohi,
                                                 __half* __restrict__ olo) {
    int row = blockIdx.x;
    int tid = threadIdx.x;
    const float4* xr = reinterpret_cast<const float4*>(x + (size_t)row * DIM);
    float4 v = xr[tid];
    float s  = v.x + v.y + v.z + v.w;
    float ss = v.x * v.x + v.y * v.y + v.z * v.z + v.w * v.w;
#pragma unroll
    for (int off = 16; off > 0; off >>= 1) {
        s  += __shfl_xor_sync(0xffffffffu, s,  off);
        ss += __shfl_xor_sync(0xffffffffu, ss, off);
    }
    __shared__ float sm[8], sm2[8];
    __shared__ float mu_sh, rstd_sh;
    int wid = tid >> 5, lane = tid & 31;
    if (lane == 0) { sm[wid] = s; sm2[wid] = ss; }
    __syncthreads();
    if (tid == 0) {
        float ts = 0.f, tss = 0.f;
#pragma unroll
        for (int i = 0; i < 8; i++) { ts += sm[i]; tss += sm2[i]; }
        float mu  = ts * (1.0f / DIM);
        float var = tss * (1.0f / DIM) - mu * mu;
        mu_sh   = mu;
        rstd_sh = rsqrtf(var + 1e-5f);
    }
    __syncthreads();
    float mu = mu_sh, rstd = rstd_sh;
    float4 wv = reinterpret_cast<const float4*>(w)[tid];
    float4 bv = reinterpret_cast<const float4*>(b)[tid];
    float o[4];
    o[0] = (v.x - mu) * rstd * wv.x + bv.x;
    o[1] = (v.y - mu) * rstd * wv.y + bv.y;
    o[2] = (v.z - mu) * rstd * wv.z + bv.z;
    o[3] = (v.w - mu) * rstd * wv.w + bv.w;
    uint2 uh, ul;
    split2h(o[0], o[1], uh.x, ul.x);
    split2h(o[2], o[3], uh.y, ul.y);
    size_t base = (size_t)row * DIM + tid * 4;
    *reinterpret_cast<uint2*>(ohi + base) = uh;
    *reinterpret_cast<uint2*>(olo + base) = ul;
}

// ---------------- weight transpose: [R,C] fp32 -> [C,R] fp16 ---------------
__global__ void __launch_bounds__(256) tsplit_kernel(const float* __restrict__ src,
                                                     __half* __restrict__ dst,
                                                     int R, int C) {
    __shared__ float t[32][33];
    int c0 = blockIdx.x * 32, r0 = blockIdx.y * 32;
    int x = threadIdx.x & 31, y = threadIdx.x >> 5;
#pragma unroll
    for (int i = 0; i < 32; i += 8)
        t[y + i][x] = src[(size_t)(r0 + y + i) * C + c0 + x];
    __syncthreads();
#pragma unroll
    for (int i = 0; i < 32; i += 8) {
        size_t o = (size_t)(c0 + y + i) * R + r0 + x;
        dst[o] = __float2half_rn(t[x][y + i]);
    }
}

// ---------------- qkv weights [H,D,HD]x3 -> [3072, 1024] fp16 --------------
__global__ void __launch_bounds__(256) qkv_tsplit_kernel(const float* __restrict__ wq,
                                                         const float* __restrict__ wk,
                                                         const float* __restrict__ wv,
                                                         __half* __restrict__ dst) {
    __shared__ float t[32][33];
    int k0 = blockIdx.x * 32;
    int n0 = blockIdx.y * 32;
    int m = n0 >> 10, h = (n0 >> 6) & 15, e0 = n0 & 63;
    const float* src = (m == 0) ? wq : (m == 1) ? wk : wv;
    int x = threadIdx.x & 31, y = threadIdx.x >> 5;
#pragma unroll
    for (int j = 0; j < 32; j += 8)
        t[y + j][x] = src[((size_t)h * DIM + k0 + y + j) * HDIM + e0 + x];
    __syncthreads();
#pragma unroll
    for (int i = 0; i < 32; i += 8) {
        size_t o = (size_t)(n0 + y + i) * DIM + k0 + x;
        dst[o] = __float2half_rn(t[x][y + i]);
    }
}

// ---------------- MMA GEMM: C[M,N] = (Ahi+Alo)[M,K] @ B[N,K]^T -------------
// fp16x2 split, fp32 accum via mma.m16n8k16.
// 128x128x32 CTA tile, 8 warps (2x4), warp tile 64x32, 3-stage cp.async.
#define PADB    80      // padded row stride in bytes (32 fp16 + 8 pad)
#define TILE_B  (128 * PADB)            // 10240 B per tile
#define STAGE_B (3 * TILE_B)            // Ahi|Alo|B = 30720 B
#define NSTAGE  3
#define GSMEM   (NSTAGE * STAGE_B)      // 92160 B -> 2 CTAs/SM

__device__ __forceinline__ void stage_load(uint32_t sbase,
                                           const __half* __restrict__ Ahi,
                                           const __half* __restrict__ Alo,
                                           const __half* __restrict__ B,
                                           int bm, int bn, int k0, int K, int tid) {
#pragma unroll
    for (int p = 0; p < 2; p++) {
        int idx = tid + (p << 8);
        int row = idx >> 2;
        int c16 = idx & 3;
        uint32_t soff = (uint32_t)row * PADB + (c16 << 4);
        size_t ga = (size_t)(bm + row) * K + k0 + (c16 << 3);
        size_t gb = (size_t)(bn + row) * K + k0 + (c16 << 3);
        ldgsts16(sbase + soff,              Ahi + ga);
        ldgsts16(sbase + TILE_B + soff,     Alo + ga);
        ldgsts16(sbase + 2 * TILE_B + soff, B + gb);
    }
}

__global__ void __launch_bounds__(256, 2) gemm_mma(
    const __half* __restrict__ Ahi, const __half* __restrict__ Alo,
    const __half* __restrict__ B,
    float* __restrict__ C, __half* __restrict__ Chi, __half* __restrict__ Clo,
    const float* __restrict__ bias, const float* __restrict__ res, int relu,
    int M, int N, int K) {
    extern __shared__ char dsm[];
    int tid  = threadIdx.x;
    int wid  = tid >> 5;
    int lane = tid & 31;
    int bm = blockIdx.y * 128, bn = blockIdx.x * 128;
    int wm = (wid >> 2) * 64;      // warp row offset in tile
    int wn = (wid & 3) * 32;       // warp col offset in tile

    uint32_t sb = smem_u32(dsm);
    const int KT = K >> 5;         // k-tiles of 32

    float acc[4][4][4] = {};       // [mi][ni][reg]

    // prologue: stages 0..NSTAGE-2
#pragma unroll
    for (int s = 0; s < NSTAGE - 1; s++) {
        stage_load(sb + s * STAGE_B, Ahi, Alo, B, bm, bn, s << 5, K, tid);
        cp_commit();
    }
    cp_wait1();
    __syncthreads();

    // ldmatrix per-lane address components
    int arow = lane & 15;
    int acolb = (lane >> 4) << 4;              // (lane/16)*8 elems * 2B
    int brow = lane & 7;
    int bcolb = ((lane >> 3) & 1) << 4;

    for (int kt = 0; kt < KT; kt++) {
        uint32_t st = sb + (uint32_t)(kt % NSTAGE) * STAGE_B;
#pragma unroll
        for (int ks = 0; ks < 2; ks++) {
            int kb = ks << 5;                  // 16 elems = 32 bytes
            uint32_t bh[4][2];
#pragma unroll
            for (int ni = 0; ni < 4; ni++) {
                uint32_t rb = st + 2 * TILE_B + (uint32_t)(wn + ni * 8 + brow) * PADB + kb + bcolb;
                ldm_x2(bh[ni], rb);
            }
#pragma unroll
            for (int mi = 0; mi < 4; mi++) {
                uint32_t ahi[4], alo[4];
                uint32_t ra = st + (uint32_t)(wm + mi * 16 + arow) * PADB + kb + acolb;
                ldm_x4(ahi, ra);
                ldm_x4(alo, ra + TILE_B);
#pragma unroll
                for (int ni = 0; ni < 4; ni++) {
                    mma16816(acc[mi][ni], ahi, bh[ni]);
                    mma16816(acc[mi][ni], alo, bh[ni]);
                }
            }
        }
        // issue next stage
        int ktn = kt + NSTAGE - 1;
        if (ktn < KT)
            stage_load(sb + (uint32_t)(ktn % NSTAGE) * STAGE_B,
                       Ahi, Alo, B, bm, bn, ktn << 5, K, tid);
        cp_commit();   // empty group in tail keeps wait semantics uniform
        cp_wait1();
        __syncthreads();
    }

    // epilogue
    int gr = lane >> 2;
    int gc = (lane & 3) << 1;
#pragma unroll
    for (int mi = 0; mi < 4; mi++) {
#pragma unroll
        for (int rr = 0; rr < 2; rr++) {
            int m = bm + wm + mi * 16 + rr * 8 + gr;
            size_t crow = (size_t)m * N;
#pragma unroll
            for (int ni = 0; ni < 4; ni++) {
                int n = bn + wn + ni * 8 + gc;
                float v0 = acc[mi][ni][rr * 2 + 0];
                float v1 = acc[mi][ni][rr * 2 + 1];
                if (bias) {
                    float2 bv = *reinterpret_cast<const float2*>(bias + n);
                    v0 += bv.x; v1 += bv.y;
                }
                if (res) {
                    float2 rv = *reinterpret_cast<const float2*>(res + crow + n);
                    v0 += rv.x; v1 += rv.y;
                }
                if (relu) { v0 = fmaxf(v0, 0.f); v1 = fmaxf(v1, 0.f); }
                if (C) {
                    *reinterpret_cast<float2*>(C + crow + n) = make_float2(v0, v1);
                } else {
                    uint32_t hp, lp;
                    split2h(v0, v1, hp, lp);
                    *reinterpret_cast<uint32_t*>(Chi + crow + n) = hp;
                    *reinterpret_cast<uint32_t*>(Clo + crow + n) = lp;
                }
            }
        }
    }
}

// ---------------- Tensor-core flash attention (fp16x2, causal) -------------
// BQ=128, BKV=64, 8 warps; warp = 16 q-rows x 64 kv. Double-buffered K/V.
#define AQ      128
#define AKV     64
#define APADE   72                  // row stride in fp16 elems
#define AROWB   (APADE * 2)         // 144 B
#define QTILE_B (AQ * AROWB)        // 18432
#define KTILE_B (AKV * AROWB)       // 9216
#define ASTAGE_B (2 * KTILE_B)      // Khi|Vhi = 18432
#define ASMEM   (2 * QTILE_B + 2 * ASTAGE_B)   // 73728

__global__ void __launch_bounds__(256, 2) attn_mma(
    const __half* __restrict__ qkv_hi,
    const __half* __restrict__ qkv_lo,
    __half* __restrict__ out_hi,
    __half* __restrict__ out_lo) {
    extern __shared__ char dsm[];
    int tid  = threadIdx.x;
    int wid  = tid >> 5;
    int lane = tid & 31;
    int bh = blockIdx.y;
    int b = bh >> 4, h = bh & 15;
    int t0 = blockIdx.x * AQ;
    int wm = wid << 4;              // warp q-row offset (16 rows per warp)

    uint32_t sb   = smem_u32(dsm);
    uint32_t sQhi = sb;
    uint32_t sQlo = sb + QTILE_B;
    uint32_t sKV  = sb + 2 * QTILE_B;

    const size_t qoff = ((size_t)b * TCTX + t0) * D3 + (size_t)h * HDIM;

    // ---- prologue loads ----
    // Q tile: 128 rows x 64 fp16, hi+lo
#pragma unroll
    for (int p = 0; p < 4; p++) {
        int idx = tid + (p << 8);
        int row = idx >> 3;
        uint32_t cb = (uint32_t)(idx & 7) << 4;    // byte col
        uint32_t so = (uint32_t)row * AROWB + cb;
        size_t go = qoff + (size_t)row * D3 + (cb >> 1);
        ldgsts16(sQhi + so, qkv_hi + go);
        ldgsts16(sQlo + so, qkv_lo + go);
    }
    const int nt = (t0 >> 6) + 2;   // kv tiles of 64

    // K/V stage loader (hi only)
    auto load_stage = [&](int kt) {
        uint32_t st = sKV + (uint32_t)(kt & 1) * ASTAGE_B;
        size_t kv0 = (size_t)kt * AKV;
        size_t koff = ((size_t)b * TCTX + kv0) * D3 + DIM + (size_t)h * HDIM;
        size_t voff = koff + DIM;
        {
            int row = tid >> 3;                    // 256 threads / 8 = 32 rows... p loop
#pragma unroll
            for (int p = 0; p < 2; p++) {
                int idx = tid + (p << 8);
                int r = idx >> 3;
                uint32_t cb = (uint32_t)(idx & 7) << 4;
                uint32_t so = (uint32_t)r * AROWB + cb;
                ldgsts16(st + so,           qkv_hi + koff + (size_t)r * D3 + (cb >> 1));
                ldgsts16(st + KTILE_B + so, qkv_hi + voff + (size_t)r * D3 + (cb >> 1));
            }
            (void)row;
        }
    };
    load_stage(0);
    cp_commit();                   // G0: Q + stage0
    if (nt > 1) load_stage(1);
    cp_commit();                   // G1

    // per-thread state
    float o[8][4] = {};
    float m0 = -1e30f, m1 = -1e30f, l0 = 0.f, l1 = 0.f;
    uint32_t qhi[4][4], qlo[4][4];

    // fragment address components
    int arow  = lane & 15;
    int acolb = (lane >> 4) << 4;
    int krow  = (lane & 7) + ((lane >> 4) << 3);
    int kcolb = ((lane >> 3) & 1) << 4;
    int vrow  = (lane & 7) + (((lane >> 3) & 1) << 3);
    int vcole = (lane >> 4) << 3;   // elems

    for (int kt = 0; kt < nt; kt++) {
        cp_wait1();
        __syncthreads();
        if (kt == 0) {
            // load Q fragments once
#pragma unroll
            for (int kk = 0; kk < 4; kk++) {
                uint32_t qa = (uint32_t)(wm + arow) * AROWB + (kk << 5) + acolb;
                ldm_x4(qhi[kk], sQhi + qa);
                ldm_x4(qlo[kk], sQlo + qa);
            }
        }
        uint32_t st = sKV + (uint32_t)(kt & 1) * ASTAGE_B;
        int kv0 = kt << 6;

        // ---- S = Q K^T (fp16x2: Qhi*K + Qlo*K) ----
        float s[8][4] = {};
#pragma unroll
        for (int kk = 0; kk < 4; kk++) {
#pragma unroll
            for (int np = 0; np < 4; np++) {
                uint32_t ka = st + (uint32_t)(np * 16 + krow) * AROWB + (kk << 5) + kcolb;
                uint32_t kh[4];
                ldm_x4(kh, ka);
                mma16816(s[2 * np],     qhi[kk], kh);
                mma16816(s[2 * np],     qlo[kk], kh);
                mma16816(s[2 * np + 1], qhi[kk], kh + 2);
                mma16816(s[2 * np + 1], qlo[kk], kh + 2);
            }
        }

        // ---- scale + causal mask ----
        int rbase = t0 + wm + (lane >> 2);
        bool need_mask = (kv0 + AKV - 1) > (t0 + wm);
#pragma unroll
        for (int ni = 0; ni < 8; ni++) {
#pragma unroll
            for (int j = 0; j < 4; j++) {
                s[ni][j] *= 0.125f;
                if (need_mask) {
                    int col = kv0 + ni * 8 + ((lane & 3) << 1) + (j & 1);
                    int row = rbase + ((j >> 1) << 3);
                    if (col > row) s[ni][j] = -1e30f;
                }
            }
        }

        // ---- online softmax (rows r and r+8, warp-local) ----
        float mx0 = -1e30f, mx1 = -1e30f;
#pragma unroll
        for (int ni = 0; ni < 8; ni++) {
            mx0 = fmaxf(mx0, fmaxf(s[ni][0], s[ni][1]));
            mx1 = fmaxf(mx1, fmaxf(s[ni][2], s[ni][3]));
        }
#pragma unroll
        for (int off = 1; off < 4; off <<= 1) {
            mx0 = fmaxf(mx0, __shfl_xor_sync(0xffffffffu, mx0, off));
            mx1 = fmaxf(mx1, __shfl_xor_sync(0xffffffffu, mx1, off));
        }
        float nm0 = fmaxf(m0, mx0), nm1 = fmaxf(m1, mx1);
        float a0 = __expf(m0 - nm0), a1 = __expf(m1 - nm1);
        m0 = nm0; m1 = nm1;
        float rs0 = 0.f, rs1 = 0.f;
#pragma unroll
        for (int ni = 0; ni < 8; ni++) {
            s[ni][0] = __expf(s[ni][0] - nm0);
            s[ni][1] = __expf(s[ni][1] - nm0);
            s[ni][2] = __expf(s[ni][2] - nm1);
            s[ni][3] = __expf(s[ni][3] - nm1);
            rs0 += s[ni][0] + s[ni][1];
            rs1 += s[ni][2] + s[ni][3];
        }
#pragma unroll
        for (int off = 1; off < 4; off <<= 1) {
            rs0 += __shfl_xor_sync(0xffffffffu, rs0, off);
            rs1 += __shfl_xor_sync(0xffffffffu, rs1, off);
        }
        l0 = a0 * l0 + rs0;
        l1 = a1 * l1 + rs1;
#pragma unroll
        for (int ni = 0; ni < 8; ni++) {
            o[ni][0] *= a0; o[ni][1] *= a0;
            o[ni][2] *= a1; o[ni][3] *= a1;
        }

        // ---- O += P V (fp16x2: Phi*V + Plo*V; P from regs, V ldmatrix.trans)
        uint32_t sVhi = st + KTILE_B;
#pragma unroll
        for (int kk2 = 0; kk2 < 4; kk2++) {
            uint32_t phi[4], plo[4];
            split2h(s[2 * kk2][0],     s[2 * kk2][1],     phi[0], plo[0]);
            split2h(s[2 * kk2][2],     s[2 * kk2][3],     phi[1], plo[1]);
            split2h(s[2 * kk2 + 1][0], s[2 * kk2 + 1][1], phi[2], plo[2]);
            split2h(s[2 * kk2 + 1][2], s[2 * kk2 + 1][3], phi[3], plo[3]);
#pragma unroll
            for (int np = 0; np < 4; np++) {
                uint32_t va = sVhi + (uint32_t)(kk2 * 16 + vrow) * AROWB
                            + (uint32_t)(np * 16 + vcole) * 2;
                uint32_t vh[4];
                ldm_x4t(vh, va);
                mma16816(o[2 * np],     phi, vh);
                mma16816(o[2 * np],     plo, vh);
                mma16816(o[2 * np + 1], phi, vh + 2);
                mma16816(o[2 * np + 1], plo, vh + 2);
            }
        }
        __syncthreads();
        if (kt + 2 < nt) load_stage(kt + 2);
        cp_commit();
    }

    // ---- normalize + write fp16 hi/lo ----
    float inv0 = 1.0f / l0, inv1 = 1.0f / l1;
    int r0g = t0 + wm + (lane >> 2);
    size_t base0 = ((size_t)b * TCTX + r0g) * DIM + (size_t)h * HDIM + ((lane & 3) << 1);
    size_t base1 = base0 + 8 * DIM;
#pragma unroll
    for (int ni = 0; ni < 8; ni++) {
        uint32_t hp, lp;
        split2h(o[ni][0] * inv0, o[ni][1] * inv0, hp, lp);
        *reinterpret_cast<uint32_t*>(out_hi + base0 + ni * 8) = hp;
        *reinterpret_cast<uint32_t*>(out_lo + base0 + ni * 8) = lp;
        split2h(o[ni][2] * inv1, o[ni][3] * inv1, hp, lp);
        *reinterpret_cast<uint32_t*>(out_hi + base1 + ni * 8) = hp;
        *reinterpret_cast<uint32_t*>(out_lo + base1 + ni * 8) = lp;
    }
}

// ---------------- launch ----------------------------------------------------
extern "C" void kernel_launch(void* const* d_in, const int* in_sizes, int n_in,
                              void* d_out, int out_size) {
    const float* x      = (const float*)d_in[0];
    const float* ln1_w  = (const float*)d_in[1];
    const float* ln1_b  = (const float*)d_in[2];
    const float* wq     = (const float*)d_in[3];
    const float* wk     = (const float*)d_in[4];
    const float* wv     = (const float*)d_in[5];
    const float* w_proj = (const float*)d_in[6];
    const float* b_proj = (const float*)d_in[7];
    const float* ln2_w  = (const float*)d_in[8];
    const float* ln2_b  = (const float*)d_in[9];
    const float* w1     = (const float*)d_in[10];
    const float* b1     = (const float*)d_in[11];
    const float* w2     = (const float*)d_in[12];
    const float* b2     = (const float*)d_in[13];
    float* out = (float*)d_out;

    float *x1;
    __half *qkv_hi, *qkv_lo;
    __half *xn_hi, *xn_lo, *at_hi, *at_lo, *xn2_hi, *xn2_lo, *h_hi, *h_lo;
    __half *wqkv, *wp, *w1h, *w2h;
    cudaGetSymbolAddress((void**)&x1,     g_x1);
    cudaGetSymbolAddress((void**)&qkv_hi, g_qkv_hi);
    cudaGetSymbolAddress((void**)&qkv_lo, g_qkv_lo);
    cudaGetSymbolAddress((void**)&xn_hi,  g_xn_hi);
    cudaGetSymbolAddress((void**)&xn_lo,  g_xn_lo);
    cudaGetSymbolAddress((void**)&at_hi,  g_at_hi);
    cudaGetSymbolAddress((void**)&at_lo,  g_at_lo);
    cudaGetSymbolAddress((void**)&xn2_hi, g_xn2_hi);
    cudaGetSymbolAddress((void**)&xn2_lo, g_xn2_lo);
    cudaGetSymbolAddress((void**)&h_hi,   g_h_hi);
    cudaGetSymbolAddress((void**)&h_lo,   g_h_lo);
    cudaGetSymbolAddress((void**)&wqkv,   g_wqkv);
    cudaGetSymbolAddress((void**)&wp,     g_wp);
    cudaGetSymbolAddress((void**)&w1h,    g_w1);
    cudaGetSymbolAddress((void**)&w2h,    g_w2);

    cudaFuncSetAttribute(gemm_mma, cudaFuncAttributeMaxDynamicSharedMemorySize, GSMEM);
    cudaFuncSetAttribute(attn_mma, cudaFuncAttributeMaxDynamicSharedMemorySize, ASMEM);

    // prep: LN1 + weight repack/transpose
    ln_kernel<<<BT_ROWS, 256>>>(x, ln1_w, ln1_b, xn_hi, xn_lo);
    qkv_tsplit_kernel<<<dim3(DIM / 32, D3 / 32), 256>>>(wq, wk, wv, wqkv);
    tsplit_kernel<<<dim3(DIM / 32, DIM / 32), 256>>>(w_proj, wp, DIM, DIM);
    tsplit_kernel<<<dim3(D4 / 32, DIM / 32), 256>>>(w1, w1h, DIM, D4);
    tsplit_kernel<<<dim3(DIM / 32, D4 / 32), 256>>>(w2, w2h, D4, DIM);

    // QKV: [8192,3072] -> fp16 hi/lo
    gemm_mma<<<dim3(D3 / 128, BT_ROWS / 128), 256, GSMEM>>>(
        xn_hi, xn_lo, wqkv, nullptr, qkv_hi, qkv_lo,
        nullptr, nullptr, 0, BT_ROWS, D3, DIM);
    // tensor-core flash attention -> fp16 hi/lo
    attn_mma<<<dim3(TCTX / AQ, NB * NH), 256, ASMEM>>>(qkv_hi, qkv_lo, at_hi, at_lo);
    // proj + bias + residual(x) -> x1 fp32
    gemm_mma<<<dim3(DIM / 128, BT_ROWS / 128), 256, GSMEM>>>(
        at_hi, at_lo, wp, x1, nullptr, nullptr,
        b_proj, x, 0, BT_ROWS, DIM, DIM);
    // LN2 -> fp16 hi/lo
    ln_kernel<<<BT_ROWS, 256>>>(x1, ln2_w, ln2_b, xn2_hi, xn2_lo);
    // MLP up + bias + relu -> h fp16 hi/lo
    gemm_mma<<<dim3(D4 / 128, BT_ROWS / 128), 256, GSMEM>>>(
        xn2_hi, xn2_lo, w1h, nullptr, h_hi, h_lo,
        b1, nullptr, 1, BT_ROWS, D4, DIM);
    // MLP down + bias + residual(x1) -> out fp32
    gemm_mma<<<dim3(DIM / 128, BT_ROWS / 128), 256, GSMEM>>>(
        h_hi, h_lo, w2h, out, nullptr, nullptr,
        b2, x1, 0, BT_ROWS, DIM, D4);
}